// round 3
// baseline (speedup 1.0000x reference)
#include <cuda_runtime.h>
#include <cuda_bf16.h>
#include <math.h>

#define L 2048
#define C 256
#define NB 4
#define H 8
#define D 32
#define SD 16.0f

// ---------------- scratch (device globals; no allocation allowed) ----------------
__device__ float g_h [L*C];
__device__ float g_h1[L*C];
__device__ float g_q [L*C];
__device__ float g_k [L*C];
__device__ float g_v [L*C];
__device__ float g_ao[L*C];
__device__ float g_mid[L*4*C];
__device__ __nv_bfloat16 g_bias[(size_t)NB*H*L*L];   // 256 MB, [b*8+h][i*L+j]
__device__ float g_tc[C];
__device__ float g_ss1[NB][2*C];
__device__ float g_ss2[NB][2*C];
__device__ float g_scal[4];   // c_skip, c_out, c_in

__device__ __forceinline__ float gelu_exact(float x) {
    return 0.5f * x * (1.0f + erff(x * 0.70710678118654752f));
}

// ---------------- K0: time embedding, time MLP, adaLN cond projections ----------------
__global__ void __launch_bounds__(256) k_prep(
    const float* __restrict__ sigma,
    const float* __restrict__ tW1, const float* __restrict__ tb1,
    const float* __restrict__ tW2, const float* __restrict__ tb2,
    const float* __restrict__ a1pW, const float* __restrict__ a1pb,
    const float* __restrict__ a2pW, const float* __restrict__ a2pb)
{
    __shared__ float temb[C];
    __shared__ float hid[4*C];
    __shared__ float tcs[C];
    const int t = threadIdx.x;
    const float sg = sigma[0];
    if (t == 0) {
        float s2 = sg*sg + SD*SD;
        g_scal[0] = SD*SD / s2;          // c_skip
        g_scal[1] = sg*SD*rsqrtf(s2);    // c_out
        g_scal[2] = rsqrtf(s2);          // c_in
    }
    const float c_noise = 0.25f * logf(sg + 1e-8f);
    if (t < 128) {
        float fr = expf(-logf(10000.0f) * (float)t / 128.0f);
        float a = c_noise * fr;
        temb[t]       = cosf(a);
        temb[t + 128] = sinf(a);
    }
    __syncthreads();
    for (int r = t; r < 4*C; r += 256) {
        float acc = tb1[r];
        const float* w = tW1 + (size_t)r * C;
        for (int k2 = 0; k2 < C; k2++) acc += temb[k2] * w[k2];
        hid[r] = gelu_exact(acc);
    }
    __syncthreads();
    for (int r = t; r < C; r += 256) {
        float acc = tb2[r];
        const float* w = tW2 + (size_t)r * 4*C;
        for (int k2 = 0; k2 < 4*C; k2++) acc += hid[k2] * w[k2];
        tcs[r] = acc;
        g_tc[r] = acc;
    }
    __syncthreads();
    for (int idx = t; idx < NB*2*C; idx += 256) {
        int b = idx / (2*C), r = idx % (2*C);
        float acc1 = a1pb[b*2*C + r];
        const float* w1 = a1pW + ((size_t)b*2*C + r) * C;
        float acc2 = a2pb[b*2*C + r];
        const float* w2 = a2pW + ((size_t)b*2*C + r) * C;
        for (int k2 = 0; k2 < C; k2++) { acc1 += tcs[k2]*w1[k2]; acc2 += tcs[k2]*w2[k2]; }
        g_ss1[b][r] = acc1;
        g_ss2[b][r] = acc2;
    }
}

// ---------------- pair bias: [L*L,64] @ [64,32] -> bf16 ----------------
__global__ void __launch_bounds__(256) k_bias(const float* __restrict__ pair,
                                              const float* __restrict__ pW)
{
    __shared__ float ws[64][36];    // [k][o]
    __shared__ float As[64][132];   // [k][row-in-tile], 128 rows
    const int tid = threadIdx.x;
    for (int idx = tid; idx < 32*64; idx += 256) {
        int o = idx >> 6, k = idx & 63;
        ws[k][o] = pW[idx];         // pW[o*64+k]
    }
    const size_t row0 = (size_t)blockIdx.x * 128;
    for (int q = tid; q < 128*16; q += 256) {
        int r = q >> 4, c4 = q & 15;
        float4 v = *(const float4*)(pair + (row0 + r) * 64 + 4*c4);
        As[4*c4+0][r] = v.x; As[4*c4+1][r] = v.y;
        As[4*c4+2][r] = v.z; As[4*c4+3][r] = v.w;
    }
    __syncthreads();
    const int rx = tid & 31;    // row lane (coalesced bf16 writes)
    const int oc = tid >> 5;    // 0..7 -> 4 outputs each
    float acc[4][4] = {};
    #pragma unroll 16
    for (int k = 0; k < 64; k++) {
        float4 b4 = *(const float4*)&ws[k][4*oc];
        float a0 = As[k][rx], a1 = As[k][rx+32], a2 = As[k][rx+64], a3 = As[k][rx+96];
        acc[0][0] += a0*b4.x; acc[0][1] += a0*b4.y; acc[0][2] += a0*b4.z; acc[0][3] += a0*b4.w;
        acc[1][0] += a1*b4.x; acc[1][1] += a1*b4.y; acc[1][2] += a1*b4.z; acc[1][3] += a1*b4.w;
        acc[2][0] += a2*b4.x; acc[2][1] += a2*b4.y; acc[2][2] += a2*b4.z; acc[2][3] += a2*b4.w;
        acc[3][0] += a3*b4.x; acc[3][1] += a3*b4.y; acc[3][2] += a3*b4.z; acc[3][3] += a3*b4.w;
    }
    #pragma unroll
    for (int j = 0; j < 4; j++) {
        int o = 4*oc + j;
        size_t base = (size_t)o * (size_t)L * (size_t)L + row0;
        #pragma unroll
        for (int i = 0; i < 4; i++)
            g_bias[base + rx + 32*i] = __float2bfloat16(acc[i][j]);
    }
}

// ---------------- generic tiled SGEMM: C = A[M,K] @ B[N,K]^T (+bias)(gelu)(+res) ----------------
template<bool HAS_BIAS, bool DO_GELU, bool HAS_RES>
__global__ void __launch_bounds__(256) k_gemm(
    const float* __restrict__ A, const float* __restrict__ Bw,
    const float* __restrict__ bias, const float* __restrict__ Rsrc,
    float* __restrict__ Cout, int M, int N, int K)
{
    __shared__ float As[16][68];
    __shared__ float Bs[16][68];
    const int tid = threadIdx.x;
    const int tx = tid & 15, ty = tid >> 4;
    const int m0 = blockIdx.y * 64, n0 = blockIdx.x * 64;
    const int lr = tid >> 2, lc = tid & 3;
    float acc[4][4] = {};
    for (int k0 = 0; k0 < K; k0 += 16) {
        float4 av = *(const float4*)&A [(size_t)(m0 + lr) * K + k0 + 4*lc];
        float4 bv = *(const float4*)&Bw[(size_t)(n0 + lr) * K + k0 + 4*lc];
        As[4*lc+0][lr] = av.x; As[4*lc+1][lr] = av.y; As[4*lc+2][lr] = av.z; As[4*lc+3][lr] = av.w;
        Bs[4*lc+0][lr] = bv.x; Bs[4*lc+1][lr] = bv.y; Bs[4*lc+2][lr] = bv.z; Bs[4*lc+3][lr] = bv.w;
        __syncthreads();
        #pragma unroll
        for (int kk = 0; kk < 16; kk++) {
            float4 a = *(const float4*)&As[kk][4*ty];
            float4 b = *(const float4*)&Bs[kk][4*tx];
            acc[0][0]+=a.x*b.x; acc[0][1]+=a.x*b.y; acc[0][2]+=a.x*b.z; acc[0][3]+=a.x*b.w;
            acc[1][0]+=a.y*b.x; acc[1][1]+=a.y*b.y; acc[1][2]+=a.y*b.z; acc[1][3]+=a.y*b.w;
            acc[2][0]+=a.z*b.x; acc[2][1]+=a.z*b.y; acc[2][2]+=a.z*b.z; acc[2][3]+=a.z*b.w;
            acc[3][0]+=a.w*b.x; acc[3][1]+=a.w*b.y; acc[3][2]+=a.w*b.z; acc[3][3]+=a.w*b.w;
        }
        __syncthreads();
    }
    #pragma unroll
    for (int i = 0; i < 4; i++) {
        int row = m0 + 4*ty + i;
        #pragma unroll
        for (int j = 0; j < 4; j++) {
            int col = n0 + 4*tx + j;
            float v = acc[i][j];
            if (HAS_BIAS) v += bias[col];
            if (DO_GELU)  v = gelu_exact(v);
            if (HAS_RES)  v += Rsrc[(size_t)row * N + col];
            Cout[(size_t)row * N + col] = v;
        }
    }
}

// ---------------- coord path add: h += c_in * x @ coordW^T + coord_b ----------------
__global__ void __launch_bounds__(256) k_coord(const float* __restrict__ xn,
                                               const float* __restrict__ cW,
                                               const float* __restrict__ cb)
{
    int idx = blockIdx.x * 256 + threadIdx.x;
    int i = idx >> 8, c = idx & 255;
    float cin = g_scal[2];
    g_h[idx] += cb[c] + cin * (xn[i*3+0]*cW[c*3+0] + xn[i*3+1]*cW[c*3+1] + xn[i*3+2]*cW[c*3+2]);
}

// ---------------- adaLN: Y = LN(X)*g*(1+scale) + shift ----------------
__global__ void __launch_bounds__(256) k_adaln(const float* __restrict__ X, float* __restrict__ Y,
                                               const float* __restrict__ gw, const float* __restrict__ bw,
                                               int blk, int which)
{
    __shared__ float red[8];
    const int row = blockIdx.x, t = threadIdx.x;
    const float* ss = which ? g_ss2[blk] : g_ss1[blk];
    float x = X[(size_t)row * C + t];
    float v = x;
    #pragma unroll
    for (int off = 16; off; off >>= 1) v += __shfl_xor_sync(0xffffffffu, v, off);
    if ((t & 31) == 0) red[t >> 5] = v;
    __syncthreads();
    float mu = 0.f;
    #pragma unroll
    for (int w = 0; w < 8; w++) mu += red[w];
    mu *= (1.0f/256.0f);
    __syncthreads();
    float d = x - mu;
    v = d * d;
    #pragma unroll
    for (int off = 16; off; off >>= 1) v += __shfl_xor_sync(0xffffffffu, v, off);
    if ((t & 31) == 0) red[t >> 5] = v;
    __syncthreads();
    float var = 0.f;
    #pragma unroll
    for (int w = 0; w < 8; w++) var += red[w];
    var *= (1.0f/256.0f);
    float y = d * rsqrtf(var + 1e-5f) * gw[t] + bw[t];
    Y[(size_t)row * C + t] = y * (1.0f + ss[t]) + ss[C + t];
}

// ---------------- flash attention with precomputed bf16 bias ----------------
__global__ void __launch_bounds__(256) k_attn(int blk)
{
    const int h  = blockIdx.y;
    const int i0 = blockIdx.x * 64;
    const int tid = threadIdx.x;
    const int tx = tid & 15, ty = tid >> 4;
    __shared__ float Qs[32][68], Ks[32][68];
    __shared__ float Vs[64][34];
    __shared__ float Ps[64][68];
    const float scale = 0.17677669529663687f;  // 1/sqrt(32)

    for (int idx = tid; idx < 64*32; idx += 256) {
        int m = idx >> 5, d = idx & 31;
        Qs[d][m] = g_q[(size_t)(i0 + m) * C + h*32 + d] * scale;
    }
    float m_run[4], l_run[4], o[4][2];
    #pragma unroll
    for (int i = 0; i < 4; i++) { m_run[i] = -1e30f; l_run[i] = 0.f; o[i][0] = 0.f; o[i][1] = 0.f; }
    const __nv_bfloat16* bias = g_bias + ((size_t)blk * H + h) * (size_t)L * (size_t)L;

    for (int j0 = 0; j0 < L; j0 += 64) {
        for (int idx = tid; idx < 64*32; idx += 256) {
            int m = idx >> 5, d = idx & 31;
            Ks[d][m] = g_k[(size_t)(j0 + m) * C + h*32 + d];
            Vs[m][d] = g_v[(size_t)(j0 + m) * C + h*32 + d];
        }
        __syncthreads();
        float s[4][4] = {};
        #pragma unroll
        for (int d = 0; d < 32; d++) {
            float4 a = *(const float4*)&Qs[d][4*ty];
            float4 b = *(const float4*)&Ks[d][4*tx];
            s[0][0]+=a.x*b.x; s[0][1]+=a.x*b.y; s[0][2]+=a.x*b.z; s[0][3]+=a.x*b.w;
            s[1][0]+=a.y*b.x; s[1][1]+=a.y*b.y; s[1][2]+=a.y*b.z; s[1][3]+=a.y*b.w;
            s[2][0]+=a.z*b.x; s[2][1]+=a.z*b.y; s[2][2]+=a.z*b.z; s[2][3]+=a.z*b.w;
            s[3][0]+=a.w*b.x; s[3][1]+=a.w*b.y; s[3][2]+=a.w*b.z; s[3][3]+=a.w*b.w;
        }
        #pragma unroll
        for (int i = 0; i < 4; i++) {
            const __nv_bfloat16* bp = bias + (size_t)(i0 + 4*ty + i) * L + j0 + 4*tx;
            __nv_bfloat162 b01 = *(const __nv_bfloat162*)bp;
            __nv_bfloat162 b23 = *(const __nv_bfloat162*)(bp + 2);
            s[i][0] += __bfloat162float(b01.x); s[i][1] += __bfloat162float(b01.y);
            s[i][2] += __bfloat162float(b23.x); s[i][3] += __bfloat162float(b23.y);
        }
        float corr[4];
        #pragma unroll
        for (int i = 0; i < 4; i++) {
            float mx = fmaxf(fmaxf(s[i][0], s[i][1]), fmaxf(s[i][2], s[i][3]));
            #pragma unroll
            for (int off = 8; off; off >>= 1) mx = fmaxf(mx, __shfl_xor_sync(0xffffffffu, mx, off));
            float mnew = fmaxf(m_run[i], mx);
            float cfac = __expf(m_run[i] - mnew);
            float rs = 0.f;
            #pragma unroll
            for (int j = 0; j < 4; j++) { float p = __expf(s[i][j] - mnew); s[i][j] = p; rs += p; }
            #pragma unroll
            for (int off = 8; off; off >>= 1) rs += __shfl_xor_sync(0xffffffffu, rs, off);
            l_run[i] = l_run[i] * cfac + rs;
            m_run[i] = mnew;
            corr[i] = cfac;
        }
        #pragma unroll
        for (int i = 0; i < 4; i++)
            *(float4*)&Ps[4*ty + i][4*tx] = make_float4(s[i][0], s[i][1], s[i][2], s[i][3]);
        __syncthreads();
        #pragma unroll
        for (int i = 0; i < 4; i++) { o[i][0] *= corr[i]; o[i][1] *= corr[i]; }
        #pragma unroll 8
        for (int j = 0; j < 64; j++) {
            float2 v = *(const float2*)&Vs[j][2*tx];
            #pragma unroll
            for (int i = 0; i < 4; i++) {
                float p = Ps[4*ty + i][j];
                o[i][0] += p * v.x;
                o[i][1] += p * v.y;
            }
        }
        __syncthreads();
    }
    #pragma unroll
    for (int i = 0; i < 4; i++) {
        float inv = 1.0f / l_run[i];
        size_t base = (size_t)(i0 + 4*ty + i) * C + h*32 + 2*tx;
        g_ao[base + 0] = o[i][0] * inv;
        g_ao[base + 1] = o[i][1] * inv;
    }
}

// ---------------- final: out = c_skip*x + c_out*(h @ outW^T + b) ----------------
__global__ void __launch_bounds__(256) k_final(const float* __restrict__ xn,
                                               const float* __restrict__ oW,
                                               const float* __restrict__ ob,
                                               float* __restrict__ out)
{
    const int warp = threadIdx.x >> 5, lane = threadIdx.x & 31;
    const int row = blockIdx.x * 8 + warp;
    const float* hr = g_h + (size_t)row * C;
    #pragma unroll
    for (int c = 0; c < 3; c++) {
        float s = 0.f;
        for (int k = lane; k < C; k += 32) s += hr[k] * oW[c*C + k];
        #pragma unroll
        for (int off = 16; off; off >>= 1) s += __shfl_xor_sync(0xffffffffu, s, off);
        if (lane == 0)
            out[row*3 + c] = g_scal[0] * xn[row*3 + c] + g_scal[1] * (s + ob[c]);
    }
}

// ---------------- launcher ----------------
extern "C" void kernel_launch(void* const* d_in, const int* in_sizes, int n_in,
                              void* d_out, int out_size)
{
    const float* x_noisy  = (const float*)d_in[0];
    const float* sigma    = (const float*)d_in[1];
    const float* single   = (const float*)d_in[2];
    const float* pair     = (const float*)d_in[3];
    const float* coord_W  = (const float*)d_in[4];
    const float* coord_b  = (const float*)d_in[5];
    const float* single_W = (const float*)d_in[6];
    const float* single_b = (const float*)d_in[7];
    const float* tmlp_W1  = (const float*)d_in[8];
    const float* tmlp_b1  = (const float*)d_in[9];
    const float* tmlp_W2  = (const float*)d_in[10];
    const float* tmlp_b2  = (const float*)d_in[11];
    const float* ada1_g   = (const float*)d_in[12];
    const float* ada1_b   = (const float*)d_in[13];
    const float* ada1_pW  = (const float*)d_in[14];
    const float* ada1_pb  = (const float*)d_in[15];
    const float* qW       = (const float*)d_in[16];
    const float* kW       = (const float*)d_in[17];
    const float* vW       = (const float*)d_in[18];
    const float* pairW    = (const float*)d_in[19];
    const float* outW     = (const float*)d_in[20];
    const float* outb     = (const float*)d_in[21];
    const float* ada2_g   = (const float*)d_in[22];
    const float* ada2_b   = (const float*)d_in[23];
    const float* ada2_pW  = (const float*)d_in[24];
    const float* ada2_pb  = (const float*)d_in[25];
    const float* ffn_W1   = (const float*)d_in[26];
    const float* ffn_b1   = (const float*)d_in[27];
    const float* ffn_W2   = (const float*)d_in[28];
    const float* ffn_b2   = (const float*)d_in[29];
    const float* out_W    = (const float*)d_in[30];
    const float* out_b    = (const float*)d_in[31];
    float* out = (float*)d_out;

    float *p_h, *p_h1, *p_q, *p_k, *p_v, *p_ao, *p_mid;
    cudaGetSymbolAddress((void**)&p_h,  g_h);
    cudaGetSymbolAddress((void**)&p_h1, g_h1);
    cudaGetSymbolAddress((void**)&p_q,  g_q);
    cudaGetSymbolAddress((void**)&p_k,  g_k);
    cudaGetSymbolAddress((void**)&p_v,  g_v);
    cudaGetSymbolAddress((void**)&p_ao, g_ao);
    cudaGetSymbolAddress((void**)&p_mid, g_mid);

    k_prep<<<1, 256>>>(sigma, tmlp_W1, tmlp_b1, tmlp_W2, tmlp_b2,
                       ada1_pW, ada1_pb, ada2_pW, ada2_pb);
    k_bias<<<(L*L)/128, 256>>>(pair, pairW);
    k_gemm<true,false,false><<<dim3(C/64, L/64), 256>>>(single, single_W, single_b, nullptr, p_h, L, C, C);
    k_coord<<<L, 256>>>(x_noisy, coord_W, coord_b);

    for (int b = 0; b < NB; b++) {
        k_adaln<<<L, 256>>>(p_h, p_h1, ada1_g + b*C, ada1_b + b*C, b, 0);
        k_gemm<false,false,false><<<dim3(C/64, L/64), 256>>>(p_h1, qW + (size_t)b*C*C, nullptr, nullptr, p_q, L, C, C);
        k_gemm<false,false,false><<<dim3(C/64, L/64), 256>>>(p_h1, kW + (size_t)b*C*C, nullptr, nullptr, p_k, L, C, C);
        k_gemm<false,false,false><<<dim3(C/64, L/64), 256>>>(p_h1, vW + (size_t)b*C*C, nullptr, nullptr, p_v, L, C, C);
        k_attn<<<dim3(L/64, H), 256>>>(b);
        k_gemm<true,false,true><<<dim3(C/64, L/64), 256>>>(p_ao, outW + (size_t)b*C*C, outb + b*C, p_h, p_h, L, C, C);
        k_adaln<<<L, 256>>>(p_h, p_h1, ada2_g + b*C, ada2_b + b*C, b, 1);
        k_gemm<true,true,false><<<dim3(4*C/64, L/64), 256>>>(p_h1, ffn_W1 + (size_t)b*4*C*C, ffn_b1 + b*4*C, nullptr, p_mid, L, 4*C, C);
        k_gemm<true,false,true><<<dim3(C/64, L/64), 256>>>(p_mid, ffn_W2 + (size_t)b*4*C*C, ffn_b2 + b*C, p_h, p_h, L, C, 4*C);
    }
    k_final<<<L/8, 256>>>(x_noisy, out_W, out_b, out);
}

// round 4
// speedup vs baseline: 1.2776x; 1.2776x over previous
#include <cuda_runtime.h>
#include <cuda_bf16.h>
#include <math.h>
#include <stdint.h>

#define L 2048
#define C 256
#define NB 4
#define H 8
#define D 32
#define SD 16.0f

// ---------------- scratch (device globals; no allocation allowed) ----------------
__device__ float g_h [L*C];
__device__ float g_h1[L*C];
__device__ float g_q [L*C];
__device__ float g_k [L*C];
__device__ float g_v [L*C];
__device__ float g_ao[L*C];
__device__ float g_mid[L*4*C];
__device__ __nv_bfloat16 g_bias[(size_t)NB*H*L*L];   // 256 MB, [b*8+h][i*L+j]
__device__ float g_tc[C];
__device__ float g_ss1[NB][2*C];
__device__ float g_ss2[NB][2*C];
__device__ float g_scal[4];   // c_skip, c_out, c_in

__device__ __forceinline__ float gelu_exact(float x) {
    return 0.5f * x * (1.0f + erff(x * 0.70710678118654752f));
}

__device__ __forceinline__ uint32_t f2tf(float x) {
    uint32_t r; asm("cvt.rna.tf32.f32 %0, %1;" : "=r"(r) : "f"(x)); return r;
}
__device__ __forceinline__ float f2tff(float x) { return __uint_as_float(f2tf(x)); }

__device__ __forceinline__ void mma_tf32(float c[4],
    uint32_t a0, uint32_t a1, uint32_t a2, uint32_t a3,
    uint32_t b0, uint32_t b1)
{
    asm volatile(
        "mma.sync.aligned.m16n8k8.row.col.f32.tf32.tf32.f32 "
        "{%0,%1,%2,%3}, {%4,%5,%6,%7}, {%8,%9}, {%0,%1,%2,%3};"
        : "+f"(c[0]), "+f"(c[1]), "+f"(c[2]), "+f"(c[3])
        : "r"(a0), "r"(a1), "r"(a2), "r"(a3), "r"(b0), "r"(b1));
}

// ---------------- K0: time embedding, time MLP, adaLN cond projections ----------------
__global__ void __launch_bounds__(256) k_prep(
    const float* __restrict__ sigma,
    const float* __restrict__ tW1, const float* __restrict__ tb1,
    const float* __restrict__ tW2, const float* __restrict__ tb2,
    const float* __restrict__ a1pW, const float* __restrict__ a1pb,
    const float* __restrict__ a2pW, const float* __restrict__ a2pb)
{
    __shared__ float temb[C];
    __shared__ float hid[4*C];
    __shared__ float tcs[C];
    const int t = threadIdx.x;
    const float sg = sigma[0];
    if (t == 0) {
        float s2 = sg*sg + SD*SD;
        g_scal[0] = SD*SD / s2;          // c_skip
        g_scal[1] = sg*SD*rsqrtf(s2);    // c_out
        g_scal[2] = rsqrtf(s2);          // c_in
    }
    const float c_noise = 0.25f * logf(sg + 1e-8f);
    if (t < 128) {
        float fr = expf(-logf(10000.0f) * (float)t / 128.0f);
        float a = c_noise * fr;
        temb[t]       = cosf(a);
        temb[t + 128] = sinf(a);
    }
    __syncthreads();
    for (int r = t; r < 4*C; r += 256) {
        float acc = tb1[r];
        const float* w = tW1 + (size_t)r * C;
        for (int k2 = 0; k2 < C; k2++) acc += temb[k2] * w[k2];
        hid[r] = gelu_exact(acc);
    }
    __syncthreads();
    for (int r = t; r < C; r += 256) {
        float acc = tb2[r];
        const float* w = tW2 + (size_t)r * 4*C;
        for (int k2 = 0; k2 < 4*C; k2++) acc += hid[k2] * w[k2];
        tcs[r] = acc;
        g_tc[r] = acc;
    }
    __syncthreads();
    for (int idx = t; idx < NB*2*C; idx += 256) {
        int b = idx / (2*C), r = idx % (2*C);
        float acc1 = a1pb[b*2*C + r];
        const float* w1 = a1pW + ((size_t)b*2*C + r) * C;
        float acc2 = a2pb[b*2*C + r];
        const float* w2 = a2pW + ((size_t)b*2*C + r) * C;
        for (int k2 = 0; k2 < C; k2++) { acc1 += tcs[k2]*w1[k2]; acc2 += tcs[k2]*w2[k2]; }
        g_ss1[b][r] = acc1;
        g_ss2[b][r] = acc2;
    }
}

// ---------------- pair bias via tf32 mma: [L*L,64] @ [64,32]^T -> bf16 ----------------
// block: 128 (i,j)-rows x 32 heads (NB*H), K=64. 8 warps, each 16 rows x 32 cols.
__global__ void __launch_bounds__(256) k_bias_tc(const float* __restrict__ pair,
                                                 const float* __restrict__ pW)
{
    __shared__ float As[128][68];   // 34816 B, pad 68 -> conflict-free frags
    __shared__ float Ws[32][68];    //  8704 B
    const int tid = threadIdx.x, lane = tid & 31, warp = tid >> 5;
    const int lr = lane >> 2, lc = lane & 3;
    const size_t row0 = (size_t)blockIdx.x * 128;

    #pragma unroll
    for (int it = 0; it < 8; it++) {
        int idx = tid + 256*it;
        int r = idx >> 4, q = idx & 15;
        float4 v = *(const float4*)&pair[(row0 + r) * 64 + 4*q];
        float* dst = &As[r][4*q];
        dst[0]=f2tff(v.x); dst[1]=f2tff(v.y); dst[2]=f2tff(v.z); dst[3]=f2tff(v.w);
    }
    #pragma unroll
    for (int it = 0; it < 2; it++) {
        int idx = tid + 256*it;
        int r = idx >> 4, q = idx & 15;
        float4 v = *(const float4*)&pW[r * 64 + 4*q];
        float* dst = &Ws[r][4*q];
        dst[0]=f2tff(v.x); dst[1]=f2tff(v.y); dst[2]=f2tff(v.z); dst[3]=f2tff(v.w);
    }
    __syncthreads();

    float c[4][4] = {};
    const int arow = 16*warp + lr;
    #pragma unroll
    for (int kk = 0; kk < 64; kk += 8) {
        uint32_t a0 = __float_as_uint(As[arow  ][kk+lc]);
        uint32_t a1 = __float_as_uint(As[arow+8][kk+lc]);
        uint32_t a2 = __float_as_uint(As[arow  ][kk+4+lc]);
        uint32_t a3 = __float_as_uint(As[arow+8][kk+4+lc]);
        #pragma unroll
        for (int nt = 0; nt < 4; nt++) {
            uint32_t b0 = __float_as_uint(Ws[8*nt+lr][kk+lc]);
            uint32_t b1 = __float_as_uint(Ws[8*nt+lr][kk+4+lc]);
            mma_tf32(c[nt], a0, a1, a2, a3, b0, b1);
        }
    }
    __syncthreads();

    // stage bf16 [o][row_local] in the As memory for coalesced writes
    __nv_bfloat16* stage = (__nv_bfloat16*)&As[0][0];
    const int SP = 132;
    #pragma unroll
    for (int nt = 0; nt < 4; nt++) {
        #pragma unroll
        for (int half = 0; half < 2; half++) {
            int rloc = 16*warp + lr + 8*half;
            int col = 8*nt + 2*lc;
            stage[(col  )*SP + rloc] = __float2bfloat16(c[nt][2*half+0]);
            stage[(col+1)*SP + rloc] = __float2bfloat16(c[nt][2*half+1]);
        }
    }
    __syncthreads();
    for (int idx = tid; idx < 32*64; idx += 256) {
        int o = idx >> 6, r2 = (idx & 63) * 2;
        __nv_bfloat162 v = *(const __nv_bfloat162*)&stage[o*SP + r2];
        *(__nv_bfloat162*)&g_bias[(size_t)o * (size_t)L * (size_t)L + row0 + r2] = v;
    }
}

// ---------------- tf32 tensor-core GEMM body: C = A[M,K] @ B[N,K]^T (+bias)(gelu)(+res)
// block tile 128(M) x 64(N), k-step 32, 8 warps = 4(M) x 2(N), each warp 32x32.
template<bool HAS_BIAS, bool DO_GELU, bool HAS_RES>
__device__ __forceinline__ void gemm_body(
    const float* __restrict__ A, const float* __restrict__ Bw,
    const float* __restrict__ bias, const float* __restrict__ Rsrc,
    float* __restrict__ Cout, int M, int N, int K)
{
    __shared__ float As[128][36];   // 18432 B
    __shared__ float Bs[64][36];    //  9216 B
    const int tid = threadIdx.x, lane = tid & 31, warp = tid >> 5;
    const int wm = warp >> 1, wn = warp & 1;
    const int m0 = blockIdx.y * 128, n0 = blockIdx.x * 64;
    const int lr = lane >> 2, lc = lane & 3;
    float c[2][4][4];
    #pragma unroll
    for (int mt = 0; mt < 2; mt++)
        #pragma unroll
        for (int nt = 0; nt < 4; nt++)
            #pragma unroll
            for (int r = 0; r < 4; r++) c[mt][nt][r] = 0.f;

    for (int k0 = 0; k0 < K; k0 += 32) {
        #pragma unroll
        for (int it = 0; it < 4; it++) {
            int idx = tid + 256*it;
            int r = idx >> 3, q = idx & 7;
            float4 v = *(const float4*)&A[(size_t)(m0 + r) * K + k0 + 4*q];
            float* dst = &As[r][4*q];
            dst[0]=f2tff(v.x); dst[1]=f2tff(v.y); dst[2]=f2tff(v.z); dst[3]=f2tff(v.w);
        }
        #pragma unroll
        for (int it = 0; it < 2; it++) {
            int idx = tid + 256*it;
            int r = idx >> 3, q = idx & 7;
            float4 v = *(const float4*)&Bw[(size_t)(n0 + r) * K + k0 + 4*q];
            float* dst = &Bs[r][4*q];
            dst[0]=f2tff(v.x); dst[1]=f2tff(v.y); dst[2]=f2tff(v.z); dst[3]=f2tff(v.w);
        }
        __syncthreads();
        #pragma unroll
        for (int kk = 0; kk < 32; kk += 8) {
            uint32_t a[2][4], b[4][2];
            #pragma unroll
            for (int mt = 0; mt < 2; mt++) {
                int row = 32*wm + 16*mt + lr;
                a[mt][0] = __float_as_uint(As[row  ][kk+lc]);
                a[mt][1] = __float_as_uint(As[row+8][kk+lc]);
                a[mt][2] = __float_as_uint(As[row  ][kk+4+lc]);
                a[mt][3] = __float_as_uint(As[row+8][kk+4+lc]);
            }
            #pragma unroll
            for (int nt = 0; nt < 4; nt++) {
                int col = 32*wn + 8*nt + lr;
                b[nt][0] = __float_as_uint(Bs[col][kk+lc]);
                b[nt][1] = __float_as_uint(Bs[col][kk+4+lc]);
            }
            #pragma unroll
            for (int mt = 0; mt < 2; mt++)
                #pragma unroll
                for (int nt = 0; nt < 4; nt++)
                    mma_tf32(c[mt][nt], a[mt][0], a[mt][1], a[mt][2], a[mt][3],
                             b[nt][0], b[nt][1]);
        }
        __syncthreads();
    }
    #pragma unroll
    for (int mt = 0; mt < 2; mt++) {
        #pragma unroll
        for (int half = 0; half < 2; half++) {
            int row = m0 + 32*wm + 16*mt + lr + 8*half;
            #pragma unroll
            for (int nt = 0; nt < 4; nt++) {
                int col = n0 + 32*wn + 8*nt + 2*lc;
                float v0 = c[mt][nt][2*half+0];
                float v1 = c[mt][nt][2*half+1];
                if (HAS_BIAS) { v0 += bias[col]; v1 += bias[col+1]; }
                if (DO_GELU)  { v0 = gelu_exact(v0); v1 = gelu_exact(v1); }
                if (HAS_RES)  { v0 += Rsrc[(size_t)row*N + col]; v1 += Rsrc[(size_t)row*N + col + 1]; }
                *(float2*)&Cout[(size_t)row*N + col] = make_float2(v0, v1);
            }
        }
    }
}

template<bool HB, bool HG, bool HR>
__global__ void __launch_bounds__(256) k_gemm_tc(
    const float* __restrict__ A, const float* __restrict__ Bw,
    const float* __restrict__ bias, const float* __restrict__ Rsrc,
    float* __restrict__ Cout, int M, int N, int K)
{
    gemm_body<HB,HG,HR>(A, Bw, bias, Rsrc, Cout, M, N, K);
}

__global__ void __launch_bounds__(256) k_qkv_tc(
    const float* __restrict__ A,
    const float* __restrict__ qW, const float* __restrict__ kWp, const float* __restrict__ vW,
    float* __restrict__ q, float* __restrict__ k, float* __restrict__ v)
{
    const float* Bw = (blockIdx.z == 0) ? qW : (blockIdx.z == 1) ? kWp : vW;
    float* Cout     = (blockIdx.z == 0) ? q  : (blockIdx.z == 1) ? k  : v;
    gemm_body<false,false,false>(A, Bw, nullptr, nullptr, Cout, L, C, C);
}

// ---------------- coord path add: h += c_in * x @ coordW^T + coord_b ----------------
__global__ void __launch_bounds__(256) k_coord(const float* __restrict__ xn,
                                               const float* __restrict__ cW,
                                               const float* __restrict__ cb)
{
    int idx = blockIdx.x * 256 + threadIdx.x;
    int i = idx >> 8, c = idx & 255;
    float cin = g_scal[2];
    g_h[idx] += cb[c] + cin * (xn[i*3+0]*cW[c*3+0] + xn[i*3+1]*cW[c*3+1] + xn[i*3+2]*cW[c*3+2]);
}

// ---------------- adaLN: Y = LN(X)*g*(1+scale) + shift ----------------
__global__ void __launch_bounds__(256) k_adaln(const float* __restrict__ X, float* __restrict__ Y,
                                               const float* __restrict__ gw, const float* __restrict__ bw,
                                               int blk, int which)
{
    __shared__ float red[8];
    const int row = blockIdx.x, t = threadIdx.x;
    const float* ss = which ? g_ss2[blk] : g_ss1[blk];
    float x = X[(size_t)row * C + t];
    float v = x;
    #pragma unroll
    for (int off = 16; off; off >>= 1) v += __shfl_xor_sync(0xffffffffu, v, off);
    if ((t & 31) == 0) red[t >> 5] = v;
    __syncthreads();
    float mu = 0.f;
    #pragma unroll
    for (int w = 0; w < 8; w++) mu += red[w];
    mu *= (1.0f/256.0f);
    __syncthreads();
    float d = x - mu;
    v = d * d;
    #pragma unroll
    for (int off = 16; off; off >>= 1) v += __shfl_xor_sync(0xffffffffu, v, off);
    if ((t & 31) == 0) red[t >> 5] = v;
    __syncthreads();
    float var = 0.f;
    #pragma unroll
    for (int w = 0; w < 8; w++) var += red[w];
    var *= (1.0f/256.0f);
    float y = d * rsqrtf(var + 1e-5f) * gw[t] + bw[t];
    Y[(size_t)row * C + t] = y * (1.0f + ss[t]) + ss[C + t];
}

// ---------------- flash attention with precomputed bf16 bias ----------------
__global__ void __launch_bounds__(256) k_attn(int blk)
{
    const int h  = blockIdx.y;
    const int i0 = blockIdx.x * 64;
    const int tid = threadIdx.x;
    const int tx = tid & 15, ty = tid >> 4;
    __shared__ float Qs[32][68], Ks[32][68];
    __shared__ float Vs[64][34];
    __shared__ float Ps[64][68];
    const float scale = 0.17677669529663687f;  // 1/sqrt(32)

    for (int idx = tid; idx < 64*32; idx += 256) {
        int m = idx >> 5, d = idx & 31;
        Qs[d][m] = g_q[(size_t)(i0 + m) * C + h*32 + d] * scale;
    }
    float m_run[4], l_run[4], o[4][2];
    #pragma unroll
    for (int i = 0; i < 4; i++) { m_run[i] = -1e30f; l_run[i] = 0.f; o[i][0] = 0.f; o[i][1] = 0.f; }
    const __nv_bfloat16* bias = g_bias + ((size_t)blk * H + h) * (size_t)L * (size_t)L;

    for (int j0 = 0; j0 < L; j0 += 64) {
        for (int idx = tid; idx < 64*32; idx += 256) {
            int m = idx >> 5, d = idx & 31;
            Ks[d][m] = g_k[(size_t)(j0 + m) * C + h*32 + d];
            Vs[m][d] = g_v[(size_t)(j0 + m) * C + h*32 + d];
        }
        __syncthreads();
        float s[4][4] = {};
        #pragma unroll
        for (int d = 0; d < 32; d++) {
            float4 a = *(const float4*)&Qs[d][4*ty];
            float4 b = *(const float4*)&Ks[d][4*tx];
            s[0][0]+=a.x*b.x; s[0][1]+=a.x*b.y; s[0][2]+=a.x*b.z; s[0][3]+=a.x*b.w;
            s[1][0]+=a.y*b.x; s[1][1]+=a.y*b.y; s[1][2]+=a.y*b.z; s[1][3]+=a.y*b.w;
            s[2][0]+=a.z*b.x; s[2][1]+=a.z*b.y; s[2][2]+=a.z*b.z; s[2][3]+=a.z*b.w;
            s[3][0]+=a.w*b.x; s[3][1]+=a.w*b.y; s[3][2]+=a.w*b.z; s[3][3]+=a.w*b.w;
        }
        #pragma unroll
        for (int i = 0; i < 4; i++) {
            const __nv_bfloat16* bp = bias + (size_t)(i0 + 4*ty + i) * L + j0 + 4*tx;
            __nv_bfloat162 b01 = *(const __nv_bfloat162*)bp;
            __nv_bfloat162 b23 = *(const __nv_bfloat162*)(bp + 2);
            s[i][0] += __bfloat162float(b01.x); s[i][1] += __bfloat162float(b01.y);
            s[i][2] += __bfloat162float(b23.x); s[i][3] += __bfloat162float(b23.y);
        }
        float corr[4];
        #pragma unroll
        for (int i = 0; i < 4; i++) {
            float mx = fmaxf(fmaxf(s[i][0], s[i][1]), fmaxf(s[i][2], s[i][3]));
            #pragma unroll
            for (int off = 8; off; off >>= 1) mx = fmaxf(mx, __shfl_xor_sync(0xffffffffu, mx, off));
            float mnew = fmaxf(m_run[i], mx);
            float cfac = __expf(m_run[i] - mnew);
            float rs = 0.f;
            #pragma unroll
            for (int j = 0; j < 4; j++) { float p = __expf(s[i][j] - mnew); s[i][j] = p; rs += p; }
            #pragma unroll
            for (int off = 8; off; off >>= 1) rs += __shfl_xor_sync(0xffffffffu, rs, off);
            l_run[i] = l_run[i] * cfac + rs;
            m_run[i] = mnew;
            corr[i] = cfac;
        }
        #pragma unroll
        for (int i = 0; i < 4; i++)
            *(float4*)&Ps[4*ty + i][4*tx] = make_float4(s[i][0], s[i][1], s[i][2], s[i][3]);
        __syncthreads();
        #pragma unroll
        for (int i = 0; i < 4; i++) { o[i][0] *= corr[i]; o[i][1] *= corr[i]; }
        #pragma unroll 8
        for (int j = 0; j < 64; j++) {
            float2 v = *(const float2*)&Vs[j][2*tx];
            #pragma unroll
            for (int i = 0; i < 4; i++) {
                float p = Ps[4*ty + i][j];
                o[i][0] += p * v.x;
                o[i][1] += p * v.y;
            }
        }
        __syncthreads();
    }
    #pragma unroll
    for (int i = 0; i < 4; i++) {
        float inv = 1.0f / l_run[i];
        size_t base = (size_t)(i0 + 4*ty + i) * C + h*32 + 2*tx;
        g_ao[base + 0] = o[i][0] * inv;
        g_ao[base + 1] = o[i][1] * inv;
    }
}

// ---------------- final: out = c_skip*x + c_out*(h @ outW^T + b) ----------------
__global__ void __launch_bounds__(256) k_final(const float* __restrict__ xn,
                                               const float* __restrict__ oW,
                                               const float* __restrict__ ob,
                                               float* __restrict__ out)
{
    const int warp = threadIdx.x >> 5, lane = threadIdx.x & 31;
    const int row = blockIdx.x * 8 + warp;
    const float* hr = g_h + (size_t)row * C;
    #pragma unroll
    for (int c = 0; c < 3; c++) {
        float s = 0.f;
        for (int k = lane; k < C; k += 32) s += hr[k] * oW[c*C + k];
        #pragma unroll
        for (int off = 16; off; off >>= 1) s += __shfl_xor_sync(0xffffffffu, s, off);
        if (lane == 0)
            out[row*3 + c] = g_scal[0] * xn[row*3 + c] + g_scal[1] * (s + ob[c]);
    }
}

// ---------------- launcher ----------------
extern "C" void kernel_launch(void* const* d_in, const int* in_sizes, int n_in,
                              void* d_out, int out_size)
{
    const float* x_noisy  = (const float*)d_in[0];
    const float* sigma    = (const float*)d_in[1];
    const float* single   = (const float*)d_in[2];
    const float* pair     = (const float*)d_in[3];
    const float* coord_W  = (const float*)d_in[4];
    const float* coord_b  = (const float*)d_in[5];
    const float* single_W = (const float*)d_in[6];
    const float* single_b = (const float*)d_in[7];
    const float* tmlp_W1  = (const float*)d_in[8];
    const float* tmlp_b1  = (const float*)d_in[9];
    const float* tmlp_W2  = (const float*)d_in[10];
    const float* tmlp_b2  = (const float*)d_in[11];
    const float* ada1_g   = (const float*)d_in[12];
    const float* ada1_b   = (const float*)d_in[13];
    const float* ada1_pW  = (const float*)d_in[14];
    const float* ada1_pb  = (const float*)d_in[15];
    const float* qW       = (const float*)d_in[16];
    const float* kW       = (const float*)d_in[17];
    const float* vW       = (const float*)d_in[18];
    const float* pairW    = (const float*)d_in[19];
    const float* outW     = (const float*)d_in[20];
    const float* outb     = (const float*)d_in[21];
    const float* ada2_g   = (const float*)d_in[22];
    const float* ada2_b   = (const float*)d_in[23];
    const float* ada2_pW  = (const float*)d_in[24];
    const float* ada2_pb  = (const float*)d_in[25];
    const float* ffn_W1   = (const float*)d_in[26];
    const float* ffn_b1   = (const float*)d_in[27];
    const float* ffn_W2   = (const float*)d_in[28];
    const float* ffn_b2   = (const float*)d_in[29];
    const float* out_W    = (const float*)d_in[30];
    const float* out_b    = (const float*)d_in[31];
    float* out = (float*)d_out;

    float *p_h, *p_h1, *p_q, *p_k, *p_v, *p_ao, *p_mid;
    cudaGetSymbolAddress((void**)&p_h,  g_h);
    cudaGetSymbolAddress((void**)&p_h1, g_h1);
    cudaGetSymbolAddress((void**)&p_q,  g_q);
    cudaGetSymbolAddress((void**)&p_k,  g_k);
    cudaGetSymbolAddress((void**)&p_v,  g_v);
    cudaGetSymbolAddress((void**)&p_ao, g_ao);
    cudaGetSymbolAddress((void**)&p_mid, g_mid);

    k_prep<<<1, 256>>>(sigma, tmlp_W1, tmlp_b1, tmlp_W2, tmlp_b2,
                       ada1_pW, ada1_pb, ada2_pW, ada2_pb);
    k_bias_tc<<<(L*L)/128, 256>>>(pair, pairW);
    k_gemm_tc<true,false,false><<<dim3(C/64, L/128), 256>>>(single, single_W, single_b, nullptr, p_h, L, C, C);
    k_coord<<<L, 256>>>(x_noisy, coord_W, coord_b);

    for (int b = 0; b < NB; b++) {
        k_adaln<<<L, 256>>>(p_h, p_h1, ada1_g + b*C, ada1_b + b*C, b, 0);
        k_qkv_tc<<<dim3(C/64, L/128, 3), 256>>>(p_h1,
            qW + (size_t)b*C*C, kW + (size_t)b*C*C, vW + (size_t)b*C*C,
            p_q, p_k, p_v);
        k_attn<<<dim3(L/64, H), 256>>>(b);
        k_gemm_tc<true,false,true><<<dim3(C/64, L/128), 256>>>(p_ao, outW + (size_t)b*C*C, outb + b*C, p_h, p_h, L, C, C);
        k_adaln<<<L, 256>>>(p_h, p_h1, ada2_g + b*C, ada2_b + b*C, b, 1);
        k_gemm_tc<true,true,false><<<dim3(4*C/64, L/128), 256>>>(p_h1, ffn_W1 + (size_t)b*4*C*C, ffn_b1 + b*4*C, nullptr, p_mid, L, 4*C, C);
        k_gemm_tc<true,false,true><<<dim3(C/64, L/128), 256>>>(p_mid, ffn_W2 + (size_t)b*4*C*C, ffn_b2 + b*C, p_h, p_h, L, C, 4*C);
    }
    k_final<<<L/8, 256>>>(x_noisy, out_W, out_b, out);
}

// round 5
// speedup vs baseline: 1.6771x; 1.3126x over previous
#include <cuda_runtime.h>
#include <cuda_bf16.h>
#include <math.h>
#include <stdint.h>

#define L 2048
#define C 256
#define NB 4
#define H 8
#define D 32
#define SD 16.0f

// ---------------- scratch (device globals; no allocation allowed) ----------------
__device__ float g_h [L*C];
__device__ float g_h1[L*C];
__device__ float g_q [L*C];
__device__ float g_k [L*C];
__device__ float g_v [L*C];
__device__ float g_ao[L*C];
__device__ float g_mid[L*4*C];
__device__ __nv_bfloat16 g_bias[(size_t)NB*H*L*L];   // 256 MB, [b*8+h][i*L+j]
__device__ float g_tc[C];
__device__ float g_ss1[NB][2*C];
__device__ float g_ss2[NB][2*C];
__device__ float g_scal[4];   // c_skip, c_out, c_in

__device__ __forceinline__ float gelu_exact(float x) {
    return 0.5f * x * (1.0f + erff(x * 0.70710678118654752f));
}

__device__ __forceinline__ uint32_t f2tf(float x) {
    uint32_t r; asm("cvt.rna.tf32.f32 %0, %1;" : "=r"(r) : "f"(x)); return r;
}
__device__ __forceinline__ float f2tff(float x) { return __uint_as_float(f2tf(x)); }

__device__ __forceinline__ void mma_tf32(float c[4],
    uint32_t a0, uint32_t a1, uint32_t a2, uint32_t a3,
    uint32_t b0, uint32_t b1)
{
    asm volatile(
        "mma.sync.aligned.m16n8k8.row.col.f32.tf32.tf32.f32 "
        "{%0,%1,%2,%3}, {%4,%5,%6,%7}, {%8,%9}, {%0,%1,%2,%3};"
        : "+f"(c[0]), "+f"(c[1]), "+f"(c[2]), "+f"(c[3])
        : "r"(a0), "r"(a1), "r"(a2), "r"(a3), "r"(b0), "r"(b1));
}

__device__ __forceinline__ void mma_bf16(float c[4],
    uint32_t a0, uint32_t a1, uint32_t a2, uint32_t a3,
    uint32_t b0, uint32_t b1)
{
    asm volatile(
        "mma.sync.aligned.m16n8k16.row.col.f32.bf16.bf16.f32 "
        "{%0,%1,%2,%3}, {%4,%5,%6,%7}, {%8,%9}, {%0,%1,%2,%3};"
        : "+f"(c[0]), "+f"(c[1]), "+f"(c[2]), "+f"(c[3])
        : "r"(a0), "r"(a1), "r"(a2), "r"(a3), "r"(b0), "r"(b1));
}

// ---------------- K0: time embedding, time MLP, adaLN cond projections ----------------
__global__ void __launch_bounds__(256) k_prep(
    const float* __restrict__ sigma,
    const float* __restrict__ tW1, const float* __restrict__ tb1,
    const float* __restrict__ tW2, const float* __restrict__ tb2,
    const float* __restrict__ a1pW, const float* __restrict__ a1pb,
    const float* __restrict__ a2pW, const float* __restrict__ a2pb)
{
    __shared__ float temb[C];
    __shared__ float hid[4*C];
    __shared__ float tcs[C];
    const int t = threadIdx.x;
    const float sg = sigma[0];
    if (t == 0) {
        float s2 = sg*sg + SD*SD;
        g_scal[0] = SD*SD / s2;          // c_skip
        g_scal[1] = sg*SD*rsqrtf(s2);    // c_out
        g_scal[2] = rsqrtf(s2);          // c_in
    }
    const float c_noise = 0.25f * logf(sg + 1e-8f);
    if (t < 128) {
        float fr = expf(-logf(10000.0f) * (float)t / 128.0f);
        float a = c_noise * fr;
        temb[t]       = cosf(a);
        temb[t + 128] = sinf(a);
    }
    __syncthreads();
    for (int r = t; r < 4*C; r += 256) {
        float acc = tb1[r];
        const float* w = tW1 + (size_t)r * C;
        for (int k2 = 0; k2 < C; k2++) acc += temb[k2] * w[k2];
        hid[r] = gelu_exact(acc);
    }
    __syncthreads();
    for (int r = t; r < C; r += 256) {
        float acc = tb2[r];
        const float* w = tW2 + (size_t)r * 4*C;
        for (int k2 = 0; k2 < 4*C; k2++) acc += hid[k2] * w[k2];
        tcs[r] = acc;
        g_tc[r] = acc;
    }
    __syncthreads();
    for (int idx = t; idx < NB*2*C; idx += 256) {
        int b = idx / (2*C), r = idx % (2*C);
        float acc1 = a1pb[b*2*C + r];
        const float* w1 = a1pW + ((size_t)b*2*C + r) * C;
        float acc2 = a2pb[b*2*C + r];
        const float* w2 = a2pW + ((size_t)b*2*C + r) * C;
        for (int k2 = 0; k2 < C; k2++) { acc1 += tcs[k2]*w1[k2]; acc2 += tcs[k2]*w2[k2]; }
        g_ss1[b][r] = acc1;
        g_ss2[b][r] = acc2;
    }
}

// ---------------- pair bias via tf32 mma: [L*L,64] @ [64,32]^T -> bf16 ----------------
__global__ void __launch_bounds__(256) k_bias_tc(const float* __restrict__ pair,
                                                 const float* __restrict__ pW)
{
    __shared__ float As[128][68];
    __shared__ float Ws[32][68];
    const int tid = threadIdx.x, lane = tid & 31, warp = tid >> 5;
    const int lr = lane >> 2, lc = lane & 3;
    const size_t row0 = (size_t)blockIdx.x * 128;

    #pragma unroll
    for (int it = 0; it < 8; it++) {
        int idx = tid + 256*it;
        int r = idx >> 4, q = idx & 15;
        float4 v = *(const float4*)&pair[(row0 + r) * 64 + 4*q];
        float* dst = &As[r][4*q];
        dst[0]=f2tff(v.x); dst[1]=f2tff(v.y); dst[2]=f2tff(v.z); dst[3]=f2tff(v.w);
    }
    #pragma unroll
    for (int it = 0; it < 2; it++) {
        int idx = tid + 256*it;
        int r = idx >> 4, q = idx & 15;
        float4 v = *(const float4*)&pW[r * 64 + 4*q];
        float* dst = &Ws[r][4*q];
        dst[0]=f2tff(v.x); dst[1]=f2tff(v.y); dst[2]=f2tff(v.z); dst[3]=f2tff(v.w);
    }
    __syncthreads();

    float c[4][4] = {};
    const int arow = 16*warp + lr;
    #pragma unroll
    for (int kk = 0; kk < 64; kk += 8) {
        uint32_t a0 = __float_as_uint(As[arow  ][kk+lc]);
        uint32_t a1 = __float_as_uint(As[arow+8][kk+lc]);
        uint32_t a2 = __float_as_uint(As[arow  ][kk+4+lc]);
        uint32_t a3 = __float_as_uint(As[arow+8][kk+4+lc]);
        #pragma unroll
        for (int nt = 0; nt < 4; nt++) {
            uint32_t b0 = __float_as_uint(Ws[8*nt+lr][kk+lc]);
            uint32_t b1 = __float_as_uint(Ws[8*nt+lr][kk+4+lc]);
            mma_tf32(c[nt], a0, a1, a2, a3, b0, b1);
        }
    }
    __syncthreads();

    __nv_bfloat16* stage = (__nv_bfloat16*)&As[0][0];
    const int SP = 132;
    #pragma unroll
    for (int nt = 0; nt < 4; nt++) {
        #pragma unroll
        for (int half = 0; half < 2; half++) {
            int rloc = 16*warp + lr + 8*half;
            int col = 8*nt + 2*lc;
            stage[(col  )*SP + rloc] = __float2bfloat16(c[nt][2*half+0]);
            stage[(col+1)*SP + rloc] = __float2bfloat16(c[nt][2*half+1]);
        }
    }
    __syncthreads();
    for (int idx = tid; idx < 32*64; idx += 256) {
        int o = idx >> 6, r2 = (idx & 63) * 2;
        __nv_bfloat162 v = *(const __nv_bfloat162*)&stage[o*SP + r2];
        *(__nv_bfloat162*)&g_bias[(size_t)o * (size_t)L * (size_t)L + row0 + r2] = v;
    }
}

// ---------------- tf32 tensor-core GEMM body ----------------
template<bool HAS_BIAS, bool DO_GELU, bool HAS_RES>
__device__ __forceinline__ void gemm_body(
    const float* __restrict__ A, const float* __restrict__ Bw,
    const float* __restrict__ bias, const float* __restrict__ Rsrc,
    float* __restrict__ Cout, int M, int N, int K)
{
    __shared__ float As[128][36];
    __shared__ float Bs[64][36];
    const int tid = threadIdx.x, lane = tid & 31, warp = tid >> 5;
    const int wm = warp >> 1, wn = warp & 1;
    const int m0 = blockIdx.y * 128, n0 = blockIdx.x * 64;
    const int lr = lane >> 2, lc = lane & 3;
    float c[2][4][4];
    #pragma unroll
    for (int mt = 0; mt < 2; mt++)
        #pragma unroll
        for (int nt = 0; nt < 4; nt++)
            #pragma unroll
            for (int r = 0; r < 4; r++) c[mt][nt][r] = 0.f;

    for (int k0 = 0; k0 < K; k0 += 32) {
        #pragma unroll
        for (int it = 0; it < 4; it++) {
            int idx = tid + 256*it;
            int r = idx >> 3, q = idx & 7;
            float4 v = *(const float4*)&A[(size_t)(m0 + r) * K + k0 + 4*q];
            float* dst = &As[r][4*q];
            dst[0]=f2tff(v.x); dst[1]=f2tff(v.y); dst[2]=f2tff(v.z); dst[3]=f2tff(v.w);
        }
        #pragma unroll
        for (int it = 0; it < 2; it++) {
            int idx = tid + 256*it;
            int r = idx >> 3, q = idx & 7;
            float4 v = *(const float4*)&Bw[(size_t)(n0 + r) * K + k0 + 4*q];
            float* dst = &Bs[r][4*q];
            dst[0]=f2tff(v.x); dst[1]=f2tff(v.y); dst[2]=f2tff(v.z); dst[3]=f2tff(v.w);
        }
        __syncthreads();
        #pragma unroll
        for (int kk = 0; kk < 32; kk += 8) {
            uint32_t a[2][4], b[4][2];
            #pragma unroll
            for (int mt = 0; mt < 2; mt++) {
                int row = 32*wm + 16*mt + lr;
                a[mt][0] = __float_as_uint(As[row  ][kk+lc]);
                a[mt][1] = __float_as_uint(As[row+8][kk+lc]);
                a[mt][2] = __float_as_uint(As[row  ][kk+4+lc]);
                a[mt][3] = __float_as_uint(As[row+8][kk+4+lc]);
            }
            #pragma unroll
            for (int nt = 0; nt < 4; nt++) {
                int col = 32*wn + 8*nt + lr;
                b[nt][0] = __float_as_uint(Bs[col][kk+lc]);
                b[nt][1] = __float_as_uint(Bs[col][kk+4+lc]);
            }
            #pragma unroll
            for (int mt = 0; mt < 2; mt++)
                #pragma unroll
                for (int nt = 0; nt < 4; nt++)
                    mma_tf32(c[mt][nt], a[mt][0], a[mt][1], a[mt][2], a[mt][3],
                             b[nt][0], b[nt][1]);
        }
        __syncthreads();
    }
    #pragma unroll
    for (int mt = 0; mt < 2; mt++) {
        #pragma unroll
        for (int half = 0; half < 2; half++) {
            int row = m0 + 32*wm + 16*mt + lr + 8*half;
            #pragma unroll
            for (int nt = 0; nt < 4; nt++) {
                int col = n0 + 32*wn + 8*nt + 2*lc;
                float v0 = c[mt][nt][2*half+0];
                float v1 = c[mt][nt][2*half+1];
                if (HAS_BIAS) { v0 += bias[col]; v1 += bias[col+1]; }
                if (DO_GELU)  { v0 = gelu_exact(v0); v1 = gelu_exact(v1); }
                if (HAS_RES)  { v0 += Rsrc[(size_t)row*N + col]; v1 += Rsrc[(size_t)row*N + col + 1]; }
                *(float2*)&Cout[(size_t)row*N + col] = make_float2(v0, v1);
            }
        }
    }
}

template<bool HB, bool HG, bool HR>
__global__ void __launch_bounds__(256) k_gemm_tc(
    const float* __restrict__ A, const float* __restrict__ Bw,
    const float* __restrict__ bias, const float* __restrict__ Rsrc,
    float* __restrict__ Cout, int M, int N, int K)
{
    gemm_body<HB,HG,HR>(A, Bw, bias, Rsrc, Cout, M, N, K);
}

__global__ void __launch_bounds__(256) k_qkv_tc(
    const float* __restrict__ A,
    const float* __restrict__ qW, const float* __restrict__ kWp, const float* __restrict__ vW,
    float* __restrict__ q, float* __restrict__ k, float* __restrict__ v)
{
    const float* Bw = (blockIdx.z == 0) ? qW : (blockIdx.z == 1) ? kWp : vW;
    float* Cout     = (blockIdx.z == 0) ? q  : (blockIdx.z == 1) ? k  : v;
    gemm_body<false,false,false>(A, Bw, nullptr, nullptr, Cout, L, C, C);
}

// ---------------- coord path add ----------------
__global__ void __launch_bounds__(256) k_coord(const float* __restrict__ xn,
                                               const float* __restrict__ cW,
                                               const float* __restrict__ cb)
{
    int idx = blockIdx.x * 256 + threadIdx.x;
    int i = idx >> 8, c = idx & 255;
    float cin = g_scal[2];
    g_h[idx] += cb[c] + cin * (xn[i*3+0]*cW[c*3+0] + xn[i*3+1]*cW[c*3+1] + xn[i*3+2]*cW[c*3+2]);
}

// ---------------- adaLN ----------------
__global__ void __launch_bounds__(256) k_adaln(const float* __restrict__ X, float* __restrict__ Y,
                                               const float* __restrict__ gw, const float* __restrict__ bw,
                                               int blk, int which)
{
    __shared__ float red[8];
    const int row = blockIdx.x, t = threadIdx.x;
    const float* ss = which ? g_ss2[blk] : g_ss1[blk];
    float x = X[(size_t)row * C + t];
    float v = x;
    #pragma unroll
    for (int off = 16; off; off >>= 1) v += __shfl_xor_sync(0xffffffffu, v, off);
    if ((t & 31) == 0) red[t >> 5] = v;
    __syncthreads();
    float mu = 0.f;
    #pragma unroll
    for (int w = 0; w < 8; w++) mu += red[w];
    mu *= (1.0f/256.0f);
    __syncthreads();
    float d = x - mu;
    v = d * d;
    #pragma unroll
    for (int off = 16; off; off >>= 1) v += __shfl_xor_sync(0xffffffffu, v, off);
    if ((t & 31) == 0) red[t >> 5] = v;
    __syncthreads();
    float var = 0.f;
    #pragma unroll
    for (int w = 0; w < 8; w++) var += red[w];
    var *= (1.0f/256.0f);
    float y = d * rsqrtf(var + 1e-5f) * gw[t] + bw[t];
    Y[(size_t)row * C + t] = y * (1.0f + ss[t]) + ss[C + t];
}

// ---------------- tensor-core flash attention (tf32 QK^T, bf16 PV) ----------------
// grid (L/128, H). 8 warps, warp w owns rows [16w, 16w+16) of the 128-row i-tile.
// smem: Qs f32[128][36] | Ks f32[128][36] | Vt bf16[32][136] | Ps bf16[128][136]
#define ATTN_SMEM (18432 + 18432 + 8704 + 34816)
__global__ void __launch_bounds__(256) k_attn_tc(int blk)
{
    extern __shared__ char smc[];
    float* Qs = (float*)smc;
    float* Ks = (float*)(smc + 18432);
    __nv_bfloat16* Vt = (__nv_bfloat16*)(smc + 36864);
    __nv_bfloat16* Ps = (__nv_bfloat16*)(smc + 45568);

    const int h  = blockIdx.y;
    const int i0 = blockIdx.x * 128;
    const int tid = threadIdx.x, lane = tid & 31, warp = tid >> 5;
    const int lr = lane >> 2, lc = lane & 3;
    const float scale = 0.17677669529663687f;  // 1/sqrt(32)

    // load Q tile [128][32] -> tf32, pre-scaled
    #pragma unroll
    for (int it = 0; it < 4; it++) {
        int idx = tid + 256*it;
        int r = idx >> 3, q = idx & 7;
        float4 v = *(const float4*)&g_q[(size_t)(i0 + r)*C + h*32 + 4*q];
        float* dst = &Qs[r*36 + 4*q];
        dst[0]=f2tff(v.x*scale); dst[1]=f2tff(v.y*scale);
        dst[2]=f2tff(v.z*scale); dst[3]=f2tff(v.w*scale);
    }

    float m_run[2] = {-1e30f, -1e30f};
    float l_run[2] = {0.f, 0.f};
    float o[4][4];
    #pragma unroll
    for (int nt = 0; nt < 4; nt++)
        #pragma unroll
        for (int r = 0; r < 4; r++) o[nt][r] = 0.f;

    const __nv_bfloat16* bias_w = g_bias + ((size_t)blk*H + h)*(size_t)L*L
                                         + (size_t)(i0 + 16*warp)*L;
    const int arow = 16*warp + lr;

    for (int j0 = 0; j0 < L; j0 += 128) {
        // load K -> tf32 [j][d]; V -> bf16 transposed [d][j]
        #pragma unroll
        for (int it = 0; it < 4; it++) {
            int idx = tid + 256*it;
            int r = idx >> 3, q = idx & 7;
            float4 kv = *(const float4*)&g_k[(size_t)(j0 + r)*C + h*32 + 4*q];
            float* dst = &Ks[r*36 + 4*q];
            dst[0]=f2tff(kv.x); dst[1]=f2tff(kv.y); dst[2]=f2tff(kv.z); dst[3]=f2tff(kv.w);
            float4 vv = *(const float4*)&g_v[(size_t)(j0 + r)*C + h*32 + 4*q];
            Vt[(4*q+0)*136 + r] = __float2bfloat16(vv.x);
            Vt[(4*q+1)*136 + r] = __float2bfloat16(vv.y);
            Vt[(4*q+2)*136 + r] = __float2bfloat16(vv.z);
            Vt[(4*q+3)*136 + r] = __float2bfloat16(vv.w);
        }
        __syncthreads();

        // S = Q K^T : warp computes 16 x 128
        float s[16][4];
        #pragma unroll
        for (int nt = 0; nt < 16; nt++)
            #pragma unroll
            for (int r = 0; r < 4; r++) s[nt][r] = 0.f;
        #pragma unroll
        for (int kk = 0; kk < 32; kk += 8) {
            uint32_t a0 = __float_as_uint(Qs[(arow  )*36 + kk+lc]);
            uint32_t a1 = __float_as_uint(Qs[(arow+8)*36 + kk+lc]);
            uint32_t a2 = __float_as_uint(Qs[(arow  )*36 + kk+4+lc]);
            uint32_t a3 = __float_as_uint(Qs[(arow+8)*36 + kk+4+lc]);
            #pragma unroll
            for (int nt = 0; nt < 16; nt++) {
                uint32_t b0 = __float_as_uint(Ks[(8*nt+lr)*36 + kk+lc]);
                uint32_t b1 = __float_as_uint(Ks[(8*nt+lr)*36 + kk+4+lc]);
                mma_tf32(s[nt], a0, a1, a2, a3, b0, b1);
            }
        }
        // + pair bias
        #pragma unroll
        for (int nt = 0; nt < 16; nt++) {
            int j = j0 + 8*nt + 2*lc;
            __nv_bfloat162 blo = *(const __nv_bfloat162*)&bias_w[(size_t)lr*L + j];
            __nv_bfloat162 bhi = *(const __nv_bfloat162*)&bias_w[(size_t)(lr+8)*L + j];
            s[nt][0] += __bfloat162float(blo.x); s[nt][1] += __bfloat162float(blo.y);
            s[nt][2] += __bfloat162float(bhi.x); s[nt][3] += __bfloat162float(bhi.y);
        }

        // online softmax (rows lr -> s[][0..1], lr+8 -> s[][2..3])
        float mx0 = -1e30f, mx1 = -1e30f;
        #pragma unroll
        for (int nt = 0; nt < 16; nt++) {
            mx0 = fmaxf(mx0, fmaxf(s[nt][0], s[nt][1]));
            mx1 = fmaxf(mx1, fmaxf(s[nt][2], s[nt][3]));
        }
        mx0 = fmaxf(mx0, __shfl_xor_sync(0xffffffffu, mx0, 1));
        mx0 = fmaxf(mx0, __shfl_xor_sync(0xffffffffu, mx0, 2));
        mx1 = fmaxf(mx1, __shfl_xor_sync(0xffffffffu, mx1, 1));
        mx1 = fmaxf(mx1, __shfl_xor_sync(0xffffffffu, mx1, 2));
        float mn0 = fmaxf(m_run[0], mx0), mn1 = fmaxf(m_run[1], mx1);
        float cf0 = __expf(m_run[0] - mn0), cf1 = __expf(m_run[1] - mn1);
        float rs0 = 0.f, rs1 = 0.f;
        #pragma unroll
        for (int nt = 0; nt < 16; nt++) {
            float p0 = __expf(s[nt][0] - mn0);
            float p1 = __expf(s[nt][1] - mn0);
            float p2 = __expf(s[nt][2] - mn1);
            float p3 = __expf(s[nt][3] - mn1);
            rs0 += p0 + p1; rs1 += p2 + p3;
            int colw = 8*nt + 2*lc;
            *(__nv_bfloat162*)&Ps[(arow  )*136 + colw] = __floats2bfloat162_rn(p0, p1);
            *(__nv_bfloat162*)&Ps[(arow+8)*136 + colw] = __floats2bfloat162_rn(p2, p3);
        }
        rs0 += __shfl_xor_sync(0xffffffffu, rs0, 1);
        rs0 += __shfl_xor_sync(0xffffffffu, rs0, 2);
        rs1 += __shfl_xor_sync(0xffffffffu, rs1, 1);
        rs1 += __shfl_xor_sync(0xffffffffu, rs1, 2);
        l_run[0] = l_run[0]*cf0 + rs0;  m_run[0] = mn0;
        l_run[1] = l_run[1]*cf1 + rs1;  m_run[1] = mn1;
        #pragma unroll
        for (int nt = 0; nt < 4; nt++) {
            o[nt][0] *= cf0; o[nt][1] *= cf0;
            o[nt][2] *= cf1; o[nt][3] *= cf1;
        }
        __syncwarp();

        // O += P V  (bf16 m16n8k16; A rows are warp-private)
        #pragma unroll
        for (int k0 = 0; k0 < 128; k0 += 16) {
            uint32_t a0 = *(const uint32_t*)&Ps[(arow  )*136 + k0 + 2*lc];
            uint32_t a1 = *(const uint32_t*)&Ps[(arow+8)*136 + k0 + 2*lc];
            uint32_t a2 = *(const uint32_t*)&Ps[(arow  )*136 + k0 + 8 + 2*lc];
            uint32_t a3 = *(const uint32_t*)&Ps[(arow+8)*136 + k0 + 8 + 2*lc];
            #pragma unroll
            for (int nt = 0; nt < 4; nt++) {
                uint32_t b0 = *(const uint32_t*)&Vt[(8*nt+lr)*136 + k0 + 2*lc];
                uint32_t b1 = *(const uint32_t*)&Vt[(8*nt+lr)*136 + k0 + 8 + 2*lc];
                mma_bf16(o[nt], a0, a1, a2, a3, b0, b1);
            }
        }
        __syncthreads();
    }

    float inv0 = 1.0f / l_run[0], inv1 = 1.0f / l_run[1];
    #pragma unroll
    for (int nt = 0; nt < 4; nt++) {
        int d = h*32 + 8*nt + 2*lc;
        size_t r0 = (size_t)(i0 + arow) * C + d;
        size_t r1 = (size_t)(i0 + arow + 8) * C + d;
        *(float2*)&g_ao[r0] = make_float2(o[nt][0]*inv0, o[nt][1]*inv0);
        *(float2*)&g_ao[r1] = make_float2(o[nt][2]*inv1, o[nt][3]*inv1);
    }
}

// ---------------- final ----------------
__global__ void __launch_bounds__(256) k_final(const float* __restrict__ xn,
                                               const float* __restrict__ oW,
                                               const float* __restrict__ ob,
                                               float* __restrict__ out)
{
    const int warp = threadIdx.x >> 5, lane = threadIdx.x & 31;
    const int row = blockIdx.x * 8 + warp;
    const float* hr = g_h + (size_t)row * C;
    #pragma unroll
    for (int c = 0; c < 3; c++) {
        float s = 0.f;
        for (int k = lane; k < C; k += 32) s += hr[k] * oW[c*C + k];
        #pragma unroll
        for (int off = 16; off; off >>= 1) s += __shfl_xor_sync(0xffffffffu, s, off);
        if (lane == 0)
            out[row*3 + c] = g_scal[0] * xn[row*3 + c] + g_scal[1] * (s + ob[c]);
    }
}

// ---------------- launcher ----------------
extern "C" void kernel_launch(void* const* d_in, const int* in_sizes, int n_in,
                              void* d_out, int out_size)
{
    const float* x_noisy  = (const float*)d_in[0];
    const float* sigma    = (const float*)d_in[1];
    const float* single   = (const float*)d_in[2];
    const float* pair     = (const float*)d_in[3];
    const float* coord_W  = (const float*)d_in[4];
    const float* coord_b  = (const float*)d_in[5];
    const float* single_W = (const float*)d_in[6];
    const float* single_b = (const float*)d_in[7];
    const float* tmlp_W1  = (const float*)d_in[8];
    const float* tmlp_b1  = (const float*)d_in[9];
    const float* tmlp_W2  = (const float*)d_in[10];
    const float* tmlp_b2  = (const float*)d_in[11];
    const float* ada1_g   = (const float*)d_in[12];
    const float* ada1_b   = (const float*)d_in[13];
    const float* ada1_pW  = (const float*)d_in[14];
    const float* ada1_pb  = (const float*)d_in[15];
    const float* qW       = (const float*)d_in[16];
    const float* kW       = (const float*)d_in[17];
    const float* vW       = (const float*)d_in[18];
    const float* pairW    = (const float*)d_in[19];
    const float* outW     = (const float*)d_in[20];
    const float* outb     = (const float*)d_in[21];
    const float* ada2_g   = (const float*)d_in[22];
    const float* ada2_b   = (const float*)d_in[23];
    const float* ada2_pW  = (const float*)d_in[24];
    const float* ada2_pb  = (const float*)d_in[25];
    const float* ffn_W1   = (const float*)d_in[26];
    const float* ffn_b1   = (const float*)d_in[27];
    const float* ffn_W2   = (const float*)d_in[28];
    const float* ffn_b2   = (const float*)d_in[29];
    const float* out_W    = (const float*)d_in[30];
    const float* out_b    = (const float*)d_in[31];
    float* out = (float*)d_out;

    float *p_h, *p_h1, *p_q, *p_k, *p_v, *p_ao, *p_mid;
    cudaGetSymbolAddress((void**)&p_h,  g_h);
    cudaGetSymbolAddress((void**)&p_h1, g_h1);
    cudaGetSymbolAddress((void**)&p_q,  g_q);
    cudaGetSymbolAddress((void**)&p_k,  g_k);
    cudaGetSymbolAddress((void**)&p_v,  g_v);
    cudaGetSymbolAddress((void**)&p_ao, g_ao);
    cudaGetSymbolAddress((void**)&p_mid, g_mid);

    static int smem_set = 0;
    if (!smem_set) {
        cudaFuncSetAttribute(k_attn_tc, cudaFuncAttributeMaxDynamicSharedMemorySize, ATTN_SMEM);
        smem_set = 1;
    }

    k_prep<<<1, 256>>>(sigma, tmlp_W1, tmlp_b1, tmlp_W2, tmlp_b2,
                       ada1_pW, ada1_pb, ada2_pW, ada2_pb);
    k_bias_tc<<<(L*L)/128, 256>>>(pair, pairW);
    k_gemm_tc<true,false,false><<<dim3(C/64, L/128), 256>>>(single, single_W, single_b, nullptr, p_h, L, C, C);
    k_coord<<<L, 256>>>(x_noisy, coord_W, coord_b);

    for (int b = 0; b < NB; b++) {
        k_adaln<<<L, 256>>>(p_h, p_h1, ada1_g + b*C, ada1_b + b*C, b, 0);
        k_qkv_tc<<<dim3(C/64, L/128, 3), 256>>>(p_h1,
            qW + (size_t)b*C*C, kW + (size_t)b*C*C, vW + (size_t)b*C*C,
            p_q, p_k, p_v);
        k_attn_tc<<<dim3(L/128, H), 256, ATTN_SMEM>>>(b);
        k_gemm_tc<true,false,true><<<dim3(C/64, L/128), 256>>>(p_ao, outW + (size_t)b*C*C, outb + b*C, p_h, p_h, L, C, C);
        k_adaln<<<L, 256>>>(p_h, p_h1, ada2_g + b*C, ada2_b + b*C, b, 1);
        k_gemm_tc<true,true,false><<<dim3(4*C/64, L/128), 256>>>(p_h1, ffn_W1 + (size_t)b*4*C*C, ffn_b1 + b*4*C, nullptr, p_mid, L, 4*C, C);
        k_gemm_tc<true,false,true><<<dim3(C/64, L/128), 256>>>(p_mid, ffn_W2 + (size_t)b*4*C*C, ffn_b2 + b*C, p_h, p_h, L, C, 4*C);
    }
    k_final<<<L/8, 256>>>(x_noisy, out_W, out_b, out);
}

// round 6
// speedup vs baseline: 1.7308x; 1.0320x over previous
#include <cuda_runtime.h>
#include <cuda_bf16.h>
#include <math.h>
#include <stdint.h>

#define L 2048
#define C 256
#define NB 4
#define H 8
#define D 32
#define SD 16.0f

// ---------------- scratch (device globals; no allocation allowed) ----------------
__device__ float g_h [L*C];
__device__ float g_h1[L*C];
__device__ float g_q [L*C];
__device__ float g_k [L*C];
__device__ float g_v [L*C];
__device__ float g_ao[L*C];
__device__ float g_mid[L*4*C];
__device__ __nv_bfloat16 g_bias[(size_t)NB*H*L*L];   // 256 MB, [b*8+h][i*L+j]
__device__ float g_tc[C];
__device__ float g_ss1[NB][2*C];
__device__ float g_ss2[NB][2*C];
__device__ float g_scal[4];   // c_skip, c_out, c_in

__device__ __forceinline__ float gelu_exact(float x) {
    return 0.5f * x * (1.0f + erff(x * 0.70710678118654752f));
}

__device__ __forceinline__ void mma_tf32(float c[4],
    uint32_t a0, uint32_t a1, uint32_t a2, uint32_t a3,
    uint32_t b0, uint32_t b1)
{
    asm volatile(
        "mma.sync.aligned.m16n8k8.row.col.f32.tf32.tf32.f32 "
        "{%0,%1,%2,%3}, {%4,%5,%6,%7}, {%8,%9}, {%0,%1,%2,%3};"
        : "+f"(c[0]), "+f"(c[1]), "+f"(c[2]), "+f"(c[3])
        : "r"(a0), "r"(a1), "r"(a2), "r"(a3), "r"(b0), "r"(b1));
}

__device__ __forceinline__ void mma_bf16(float c[4],
    uint32_t a0, uint32_t a1, uint32_t a2, uint32_t a3,
    uint32_t b0, uint32_t b1)
{
    asm volatile(
        "mma.sync.aligned.m16n8k16.row.col.f32.bf16.bf16.f32 "
        "{%0,%1,%2,%3}, {%4,%5,%6,%7}, {%8,%9}, {%0,%1,%2,%3};"
        : "+f"(c[0]), "+f"(c[1]), "+f"(c[2]), "+f"(c[3])
        : "r"(a0), "r"(a1), "r"(a2), "r"(a3), "r"(b0), "r"(b1));
}

__device__ __forceinline__ void cp16(float* smem_dst, const float* gsrc) {
    uint32_t s = (uint32_t)__cvta_generic_to_shared(smem_dst);
    asm volatile("cp.async.cg.shared.global [%0], [%1], 16;" :: "r"(s), "l"(gsrc));
}
#define CP_COMMIT() asm volatile("cp.async.commit_group;")
#define CP_WAIT(n)  asm volatile("cp.async.wait_group %0;" :: "n"(n))

// ---------------- K0: time embedding, time MLP, adaLN cond projections ----------------
__global__ void __launch_bounds__(256) k_prep(
    const float* __restrict__ sigma,
    const float* __restrict__ tW1, const float* __restrict__ tb1,
    const float* __restrict__ tW2, const float* __restrict__ tb2,
    const float* __restrict__ a1pW, const float* __restrict__ a1pb,
    const float* __restrict__ a2pW, const float* __restrict__ a2pb)
{
    __shared__ float temb[C];
    __shared__ float hid[4*C];
    __shared__ float tcs[C];
    const int t = threadIdx.x;
    const float sg = sigma[0];
    if (t == 0) {
        float s2 = sg*sg + SD*SD;
        g_scal[0] = SD*SD / s2;          // c_skip
        g_scal[1] = sg*SD*rsqrtf(s2);    // c_out
        g_scal[2] = rsqrtf(s2);          // c_in
    }
    const float c_noise = 0.25f * logf(sg + 1e-8f);
    if (t < 128) {
        float fr = expf(-logf(10000.0f) * (float)t / 128.0f);
        float a = c_noise * fr;
        temb[t]       = cosf(a);
        temb[t + 128] = sinf(a);
    }
    __syncthreads();
    for (int r = t; r < 4*C; r += 256) {
        float acc = tb1[r];
        const float* w = tW1 + (size_t)r * C;
        for (int k2 = 0; k2 < C; k2++) acc += temb[k2] * w[k2];
        hid[r] = gelu_exact(acc);
    }
    __syncthreads();
    for (int r = t; r < C; r += 256) {
        float acc = tb2[r];
        const float* w = tW2 + (size_t)r * 4*C;
        for (int k2 = 0; k2 < 4*C; k2++) acc += hid[k2] * w[k2];
        tcs[r] = acc;
        g_tc[r] = acc;
    }
    __syncthreads();
    for (int idx = t; idx < NB*2*C; idx += 256) {
        int b = idx / (2*C), r = idx % (2*C);
        float acc1 = a1pb[b*2*C + r];
        const float* w1 = a1pW + ((size_t)b*2*C + r) * C;
        float acc2 = a2pb[b*2*C + r];
        const float* w2 = a2pW + ((size_t)b*2*C + r) * C;
        for (int k2 = 0; k2 < C; k2++) { acc1 += tcs[k2]*w1[k2]; acc2 += tcs[k2]*w2[k2]; }
        g_ss1[b][r] = acc1;
        g_ss2[b][r] = acc2;
    }
}

// ---------------- pair bias via tf32 mma: [L*L,64] @ [64,32]^T -> bf16 ----------------
__global__ void __launch_bounds__(256) k_bias_tc(const float* __restrict__ pair,
                                                 const float* __restrict__ pW)
{
    __shared__ float As[128][68];
    __shared__ float Ws[32][68];
    const int tid = threadIdx.x, lane = tid & 31, warp = tid >> 5;
    const int lr = lane >> 2, lc = lane & 3;
    const size_t row0 = (size_t)blockIdx.x * 128;

    #pragma unroll
    for (int it = 0; it < 8; it++) {
        int idx = tid + 256*it;
        int r = idx >> 4, q = idx & 15;
        float4 v = *(const float4*)&pair[(row0 + r) * 64 + 4*q];
        *(float4*)&As[r][4*q] = v;
    }
    #pragma unroll
    for (int it = 0; it < 2; it++) {
        int idx = tid + 256*it;
        int r = idx >> 4, q = idx & 15;
        float4 v = *(const float4*)&pW[r * 64 + 4*q];
        *(float4*)&Ws[r][4*q] = v;
    }
    __syncthreads();

    float c[4][4] = {};
    const int arow = 16*warp + lr;
    #pragma unroll
    for (int kk = 0; kk < 64; kk += 8) {
        uint32_t a0 = __float_as_uint(As[arow  ][kk+lc]);
        uint32_t a1 = __float_as_uint(As[arow+8][kk+lc]);
        uint32_t a2 = __float_as_uint(As[arow  ][kk+4+lc]);
        uint32_t a3 = __float_as_uint(As[arow+8][kk+4+lc]);
        #pragma unroll
        for (int nt = 0; nt < 4; nt++) {
            uint32_t b0 = __float_as_uint(Ws[8*nt+lr][kk+lc]);
            uint32_t b1 = __float_as_uint(Ws[8*nt+lr][kk+4+lc]);
            mma_tf32(c[nt], a0, a1, a2, a3, b0, b1);
        }
    }
    __syncthreads();

    __nv_bfloat16* stage = (__nv_bfloat16*)&As[0][0];
    const int SP = 132;
    #pragma unroll
    for (int nt = 0; nt < 4; nt++) {
        #pragma unroll
        for (int half = 0; half < 2; half++) {
            int rloc = 16*warp + lr + 8*half;
            int col = 8*nt + 2*lc;
            stage[(col  )*SP + rloc] = __float2bfloat16(c[nt][2*half+0]);
            stage[(col+1)*SP + rloc] = __float2bfloat16(c[nt][2*half+1]);
        }
    }
    __syncthreads();
    for (int idx = tid; idx < 32*64; idx += 256) {
        int o = idx >> 6, r2 = (idx & 63) * 2;
        __nv_bfloat162 v = *(const __nv_bfloat162*)&stage[o*SP + r2];
        *(__nv_bfloat162*)&g_bias[(size_t)o * (size_t)L * (size_t)L + row0 + r2] = v;
    }
}

// ---------------- tf32 GEMM, 128x128 tile, cp.async double-buffered ----------------
// 8 warps = 4(M) x 2(N); warp tile 32x64. smem 2*(128+128)*36 floats = 72KB dynamic.
#define GSTAGE (128*36)
#define GEMM_SMEM (4*GSTAGE*4)

template<bool HAS_BIAS, bool DO_GELU, bool HAS_RES>
__device__ __forceinline__ void gemm_body128(
    const float* __restrict__ A, const float* __restrict__ Bw,
    const float* __restrict__ bias, const float* __restrict__ Rsrc,
    float* __restrict__ Cout, int M, int N, int K)
{
    extern __shared__ float sm[];
    float* AsB = sm;                 // [2][128][36]
    float* BsB = sm + 2*GSTAGE;      // [2][128][36]
    const int tid = threadIdx.x, lane = tid & 31, warp = tid >> 5;
    const int wm = warp >> 1, wn = warp & 1;
    const int m0 = blockIdx.y * 128, n0 = blockIdx.x * 128;
    const int lr = lane >> 2, lc = lane & 3;
    const int pr = tid >> 3, pq = tid & 7;   // prefetch row base / quad

    float c[2][8][4];
    #pragma unroll
    for (int mt = 0; mt < 2; mt++)
        #pragma unroll
        for (int nt = 0; nt < 8; nt++)
            #pragma unroll
            for (int r = 0; r < 4; r++) c[mt][nt][r] = 0.f;

    const int NK = K >> 5;
    // prefetch stage 0
    {
        float* as = AsB; float* bs = BsB;
        #pragma unroll
        for (int it = 0; it < 4; it++) {
            int r = pr + 32*it;
            cp16(&as[r*36 + 4*pq], &A [(size_t)(m0 + r)*K + 4*pq]);
            cp16(&bs[r*36 + 4*pq], &Bw[(size_t)(n0 + r)*K + 4*pq]);
        }
        CP_COMMIT();
    }

    for (int ks = 0; ks < NK; ks++) {
        if (ks + 1 < NK) {
            float* as = AsB + ((ks+1)&1)*GSTAGE;
            float* bs = BsB + ((ks+1)&1)*GSTAGE;
            int k0 = (ks+1) << 5;
            #pragma unroll
            for (int it = 0; it < 4; it++) {
                int r = pr + 32*it;
                cp16(&as[r*36 + 4*pq], &A [(size_t)(m0 + r)*K + k0 + 4*pq]);
                cp16(&bs[r*36 + 4*pq], &Bw[(size_t)(n0 + r)*K + k0 + 4*pq]);
            }
            CP_COMMIT();
            CP_WAIT(1);
        } else {
            CP_WAIT(0);
        }
        __syncthreads();
        const float* as = AsB + (ks&1)*GSTAGE;
        const float* bs = BsB + (ks&1)*GSTAGE;
        #pragma unroll
        for (int kk = 0; kk < 32; kk += 8) {
            uint32_t a[2][4], b[8][2];
            #pragma unroll
            for (int mt = 0; mt < 2; mt++) {
                int row = 32*wm + 16*mt + lr;
                a[mt][0] = __float_as_uint(as[(row  )*36 + kk+lc]);
                a[mt][1] = __float_as_uint(as[(row+8)*36 + kk+lc]);
                a[mt][2] = __float_as_uint(as[(row  )*36 + kk+4+lc]);
                a[mt][3] = __float_as_uint(as[(row+8)*36 + kk+4+lc]);
            }
            #pragma unroll
            for (int nt = 0; nt < 8; nt++) {
                int col = 64*wn + 8*nt + lr;
                b[nt][0] = __float_as_uint(bs[col*36 + kk+lc]);
                b[nt][1] = __float_as_uint(bs[col*36 + kk+4+lc]);
            }
            #pragma unroll
            for (int mt = 0; mt < 2; mt++)
                #pragma unroll
                for (int nt = 0; nt < 8; nt++)
                    mma_tf32(c[mt][nt], a[mt][0], a[mt][1], a[mt][2], a[mt][3],
                             b[nt][0], b[nt][1]);
        }
        __syncthreads();
    }

    #pragma unroll
    for (int mt = 0; mt < 2; mt++) {
        #pragma unroll
        for (int half = 0; half < 2; half++) {
            int row = m0 + 32*wm + 16*mt + lr + 8*half;
            #pragma unroll
            for (int nt = 0; nt < 8; nt++) {
                int col = n0 + 64*wn + 8*nt + 2*lc;
                float v0 = c[mt][nt][2*half+0];
                float v1 = c[mt][nt][2*half+1];
                if (HAS_BIAS) { v0 += bias[col]; v1 += bias[col+1]; }
                if (DO_GELU)  { v0 = gelu_exact(v0); v1 = gelu_exact(v1); }
                if (HAS_RES)  { v0 += Rsrc[(size_t)row*N + col]; v1 += Rsrc[(size_t)row*N + col + 1]; }
                *(float2*)&Cout[(size_t)row*N + col] = make_float2(v0, v1);
            }
        }
    }
}

template<bool HB, bool HG, bool HR>
__global__ void __launch_bounds__(256, 2) k_gemm_tc(
    const float* __restrict__ A, const float* __restrict__ Bw,
    const float* __restrict__ bias, const float* __restrict__ Rsrc,
    float* __restrict__ Cout, int M, int N, int K)
{
    gemm_body128<HB,HG,HR>(A, Bw, bias, Rsrc, Cout, M, N, K);
}

__global__ void __launch_bounds__(256, 2) k_qkv_tc(
    const float* __restrict__ A,
    const float* __restrict__ qW, const float* __restrict__ kWp, const float* __restrict__ vW,
    float* __restrict__ q, float* __restrict__ k, float* __restrict__ v)
{
    const float* Bw = (blockIdx.z == 0) ? qW : (blockIdx.z == 1) ? kWp : vW;
    float* Cout     = (blockIdx.z == 0) ? q  : (blockIdx.z == 1) ? k  : v;
    gemm_body128<false,false,false>(A, Bw, nullptr, nullptr, Cout, L, C, C);
}

// ---------------- coord path add ----------------
__global__ void __launch_bounds__(256) k_coord(const float* __restrict__ xn,
                                               const float* __restrict__ cW,
                                               const float* __restrict__ cb)
{
    int idx = blockIdx.x * 256 + threadIdx.x;
    int i = idx >> 8, c = idx & 255;
    float cin = g_scal[2];
    g_h[idx] += cb[c] + cin * (xn[i*3+0]*cW[c*3+0] + xn[i*3+1]*cW[c*3+1] + xn[i*3+2]*cW[c*3+2]);
}

// ---------------- adaLN ----------------
__global__ void __launch_bounds__(256) k_adaln(const float* __restrict__ X, float* __restrict__ Y,
                                               const float* __restrict__ gw, const float* __restrict__ bw,
                                               int blk, int which)
{
    __shared__ float red[8];
    const int row = blockIdx.x, t = threadIdx.x;
    const float* ss = which ? g_ss2[blk] : g_ss1[blk];
    float x = X[(size_t)row * C + t];
    float v = x;
    #pragma unroll
    for (int off = 16; off; off >>= 1) v += __shfl_xor_sync(0xffffffffu, v, off);
    if ((t & 31) == 0) red[t >> 5] = v;
    __syncthreads();
    float mu = 0.f;
    #pragma unroll
    for (int w = 0; w < 8; w++) mu += red[w];
    mu *= (1.0f/256.0f);
    __syncthreads();
    float d = x - mu;
    v = d * d;
    #pragma unroll
    for (int off = 16; off; off >>= 1) v += __shfl_xor_sync(0xffffffffu, v, off);
    if ((t & 31) == 0) red[t >> 5] = v;
    __syncthreads();
    float var = 0.f;
    #pragma unroll
    for (int w = 0; w < 8; w++) var += red[w];
    var *= (1.0f/256.0f);
    float y = d * rsqrtf(var + 1e-5f) * gw[t] + bw[t];
    Y[(size_t)row * C + t] = y * (1.0f + ss[t]) + ss[C + t];
}

// ---------------- tensor-core flash attention (tf32 QK^T, bf16 PV) ----------------
#define ATTN_SMEM (18432 + 18432 + 8704 + 34816)
__global__ void __launch_bounds__(256) k_attn_tc(int blk)
{
    extern __shared__ char smc[];
    float* Qs = (float*)smc;
    float* Ks = (float*)(smc + 18432);
    __nv_bfloat16* Vt = (__nv_bfloat16*)(smc + 36864);
    __nv_bfloat16* Ps = (__nv_bfloat16*)(smc + 45568);

    const int h  = blockIdx.y;
    const int i0 = blockIdx.x * 128;
    const int tid = threadIdx.x, lane = tid & 31, warp = tid >> 5;
    const int lr = lane >> 2, lc = lane & 3;
    const float scale = 0.17677669529663687f;  // 1/sqrt(32)

    #pragma unroll
    for (int it = 0; it < 4; it++) {
        int idx = tid + 256*it;
        int r = idx >> 3, q = idx & 7;
        float4 v = *(const float4*)&g_q[(size_t)(i0 + r)*C + h*32 + 4*q];
        float* dst = &Qs[r*36 + 4*q];
        dst[0]=v.x*scale; dst[1]=v.y*scale; dst[2]=v.z*scale; dst[3]=v.w*scale;
    }

    float m_run[2] = {-1e30f, -1e30f};
    float l_run[2] = {0.f, 0.f};
    float o[4][4];
    #pragma unroll
    for (int nt = 0; nt < 4; nt++)
        #pragma unroll
        for (int r = 0; r < 4; r++) o[nt][r] = 0.f;

    const __nv_bfloat16* bias_w = g_bias + ((size_t)blk*H + h)*(size_t)L*L
                                         + (size_t)(i0 + 16*warp)*L;
    const int arow = 16*warp + lr;

    for (int j0 = 0; j0 < L; j0 += 128) {
        #pragma unroll
        for (int it = 0; it < 4; it++) {
            int idx = tid + 256*it;
            int r = idx >> 3, q = idx & 7;
            float4 kv = *(const float4*)&g_k[(size_t)(j0 + r)*C + h*32 + 4*q];
            *(float4*)&Ks[r*36 + 4*q] = kv;
            float4 vv = *(const float4*)&g_v[(size_t)(j0 + r)*C + h*32 + 4*q];
            Vt[(4*q+0)*136 + r] = __float2bfloat16(vv.x);
            Vt[(4*q+1)*136 + r] = __float2bfloat16(vv.y);
            Vt[(4*q+2)*136 + r] = __float2bfloat16(vv.z);
            Vt[(4*q+3)*136 + r] = __float2bfloat16(vv.w);
        }
        __syncthreads();

        float s[16][4];
        #pragma unroll
        for (int nt = 0; nt < 16; nt++)
            #pragma unroll
            for (int r = 0; r < 4; r++) s[nt][r] = 0.f;
        #pragma unroll
        for (int kk = 0; kk < 32; kk += 8) {
            uint32_t a0 = __float_as_uint(Qs[(arow  )*36 + kk+lc]);
            uint32_t a1 = __float_as_uint(Qs[(arow+8)*36 + kk+lc]);
            uint32_t a2 = __float_as_uint(Qs[(arow  )*36 + kk+4+lc]);
            uint32_t a3 = __float_as_uint(Qs[(arow+8)*36 + kk+4+lc]);
            #pragma unroll
            for (int nt = 0; nt < 16; nt++) {
                uint32_t b0 = __float_as_uint(Ks[(8*nt+lr)*36 + kk+lc]);
                uint32_t b1 = __float_as_uint(Ks[(8*nt+lr)*36 + kk+4+lc]);
                mma_tf32(s[nt], a0, a1, a2, a3, b0, b1);
            }
        }
        #pragma unroll
        for (int nt = 0; nt < 16; nt++) {
            int j = j0 + 8*nt + 2*lc;
            __nv_bfloat162 blo = *(const __nv_bfloat162*)&bias_w[(size_t)lr*L + j];
            __nv_bfloat162 bhi = *(const __nv_bfloat162*)&bias_w[(size_t)(lr+8)*L + j];
            s[nt][0] += __bfloat162float(blo.x); s[nt][1] += __bfloat162float(blo.y);
            s[nt][2] += __bfloat162float(bhi.x); s[nt][3] += __bfloat162float(bhi.y);
        }

        float mx0 = -1e30f, mx1 = -1e30f;
        #pragma unroll
        for (int nt = 0; nt < 16; nt++) {
            mx0 = fmaxf(mx0, fmaxf(s[nt][0], s[nt][1]));
            mx1 = fmaxf(mx1, fmaxf(s[nt][2], s[nt][3]));
        }
        mx0 = fmaxf(mx0, __shfl_xor_sync(0xffffffffu, mx0, 1));
        mx0 = fmaxf(mx0, __shfl_xor_sync(0xffffffffu, mx0, 2));
        mx1 = fmaxf(mx1, __shfl_xor_sync(0xffffffffu, mx1, 1));
        mx1 = fmaxf(mx1, __shfl_xor_sync(0xffffffffu, mx1, 2));
        float mn0 = fmaxf(m_run[0], mx0), mn1 = fmaxf(m_run[1], mx1);
        float cf0 = __expf(m_run[0] - mn0), cf1 = __expf(m_run[1] - mn1);
        float rs0 = 0.f, rs1 = 0.f;
        #pragma unroll
        for (int nt = 0; nt < 16; nt++) {
            float p0 = __expf(s[nt][0] - mn0);
            float p1 = __expf(s[nt][1] - mn0);
            float p2 = __expf(s[nt][2] - mn1);
            float p3 = __expf(s[nt][3] - mn1);
            rs0 += p0 + p1; rs1 += p2 + p3;
            int colw = 8*nt + 2*lc;
            *(__nv_bfloat162*)&Ps[(arow  )*136 + colw] = __floats2bfloat162_rn(p0, p1);
            *(__nv_bfloat162*)&Ps[(arow+8)*136 + colw] = __floats2bfloat162_rn(p2, p3);
        }
        rs0 += __shfl_xor_sync(0xffffffffu, rs0, 1);
        rs0 += __shfl_xor_sync(0xffffffffu, rs0, 2);
        rs1 += __shfl_xor_sync(0xffffffffu, rs1, 1);
        rs1 += __shfl_xor_sync(0xffffffffu, rs1, 2);
        l_run[0] = l_run[0]*cf0 + rs0;  m_run[0] = mn0;
        l_run[1] = l_run[1]*cf1 + rs1;  m_run[1] = mn1;
        #pragma unroll
        for (int nt = 0; nt < 4; nt++) {
            o[nt][0] *= cf0; o[nt][1] *= cf0;
            o[nt][2] *= cf1; o[nt][3] *= cf1;
        }
        __syncwarp();

        #pragma unroll
        for (int k0 = 0; k0 < 128; k0 += 16) {
            uint32_t a0 = *(const uint32_t*)&Ps[(arow  )*136 + k0 + 2*lc];
            uint32_t a1 = *(const uint32_t*)&Ps[(arow+8)*136 + k0 + 2*lc];
            uint32_t a2 = *(const uint32_t*)&Ps[(arow  )*136 + k0 + 8 + 2*lc];
            uint32_t a3 = *(const uint32_t*)&Ps[(arow+8)*136 + k0 + 8 + 2*lc];
            #pragma unroll
            for (int nt = 0; nt < 4; nt++) {
                uint32_t b0 = *(const uint32_t*)&Vt[(8*nt+lr)*136 + k0 + 2*lc];
                uint32_t b1 = *(const uint32_t*)&Vt[(8*nt+lr)*136 + k0 + 8 + 2*lc];
                mma_bf16(o[nt], a0, a1, a2, a3, b0, b1);
            }
        }
        __syncthreads();
    }

    float inv0 = 1.0f / l_run[0], inv1 = 1.0f / l_run[1];
    #pragma unroll
    for (int nt = 0; nt < 4; nt++) {
        int d = h*32 + 8*nt + 2*lc;
        size_t r0 = (size_t)(i0 + arow) * C + d;
        size_t r1 = (size_t)(i0 + arow + 8) * C + d;
        *(float2*)&g_ao[r0] = make_float2(o[nt][0]*inv0, o[nt][1]*inv0);
        *(float2*)&g_ao[r1] = make_float2(o[nt][2]*inv1, o[nt][3]*inv1);
    }
}

// ---------------- final ----------------
__global__ void __launch_bounds__(256) k_final(const float* __restrict__ xn,
                                               const float* __restrict__ oW,
                                               const float* __restrict__ ob,
                                               float* __restrict__ out)
{
    const int warp = threadIdx.x >> 5, lane = threadIdx.x & 31;
    const int row = blockIdx.x * 8 + warp;
    const float* hr = g_h + (size_t)row * C;
    #pragma unroll
    for (int c = 0; c < 3; c++) {
        float s = 0.f;
        for (int k = lane; k < C; k += 32) s += hr[k] * oW[c*C + k];
        #pragma unroll
        for (int off = 16; off; off >>= 1) s += __shfl_xor_sync(0xffffffffu, s, off);
        if (lane == 0)
            out[row*3 + c] = g_scal[0] * xn[row*3 + c] + g_scal[1] * (s + ob[c]);
    }
}

// ---------------- launcher ----------------
extern "C" void kernel_launch(void* const* d_in, const int* in_sizes, int n_in,
                              void* d_out, int out_size)
{
    const float* x_noisy  = (const float*)d_in[0];
    const float* sigma    = (const float*)d_in[1];
    const float* single   = (const float*)d_in[2];
    const float* pair     = (const float*)d_in[3];
    const float* coord_W  = (const float*)d_in[4];
    const float* coord_b  = (const float*)d_in[5];
    const float* single_W = (const float*)d_in[6];
    const float* single_b = (const float*)d_in[7];
    const float* tmlp_W1  = (const float*)d_in[8];
    const float* tmlp_b1  = (const float*)d_in[9];
    const float* tmlp_W2  = (const float*)d_in[10];
    const float* tmlp_b2  = (const float*)d_in[11];
    const float* ada1_g   = (const float*)d_in[12];
    const float* ada1_b   = (const float*)d_in[13];
    const float* ada1_pW  = (const float*)d_in[14];
    const float* ada1_pb  = (const float*)d_in[15];
    const float* qW       = (const float*)d_in[16];
    const float* kW       = (const float*)d_in[17];
    const float* vW       = (const float*)d_in[18];
    const float* pairW    = (const float*)d_in[19];
    const float* outW     = (const float*)d_in[20];
    const float* outb     = (const float*)d_in[21];
    const float* ada2_g   = (const float*)d_in[22];
    const float* ada2_b   = (const float*)d_in[23];
    const float* ada2_pW  = (const float*)d_in[24];
    const float* ada2_pb  = (const float*)d_in[25];
    const float* ffn_W1   = (const float*)d_in[26];
    const float* ffn_b1   = (const float*)d_in[27];
    const float* ffn_W2   = (const float*)d_in[28];
    const float* ffn_b2   = (const float*)d_in[29];
    const float* out_W    = (const float*)d_in[30];
    const float* out_b    = (const float*)d_in[31];
    float* out = (float*)d_out;

    float *p_h, *p_h1, *p_q, *p_k, *p_v, *p_ao, *p_mid;
    cudaGetSymbolAddress((void**)&p_h,  g_h);
    cudaGetSymbolAddress((void**)&p_h1, g_h1);
    cudaGetSymbolAddress((void**)&p_q,  g_q);
    cudaGetSymbolAddress((void**)&p_k,  g_k);
    cudaGetSymbolAddress((void**)&p_v,  g_v);
    cudaGetSymbolAddress((void**)&p_ao, g_ao);
    cudaGetSymbolAddress((void**)&p_mid, g_mid);

    static int attr_set = 0;
    if (!attr_set) {
        cudaFuncSetAttribute(k_attn_tc, cudaFuncAttributeMaxDynamicSharedMemorySize, ATTN_SMEM);
        cudaFuncSetAttribute(k_gemm_tc<true,false,false>, cudaFuncAttributeMaxDynamicSharedMemorySize, GEMM_SMEM);
        cudaFuncSetAttribute(k_gemm_tc<true,false,true >, cudaFuncAttributeMaxDynamicSharedMemorySize, GEMM_SMEM);
        cudaFuncSetAttribute(k_gemm_tc<true,true ,false>, cudaFuncAttributeMaxDynamicSharedMemorySize, GEMM_SMEM);
        cudaFuncSetAttribute(k_qkv_tc, cudaFuncAttributeMaxDynamicSharedMemorySize, GEMM_SMEM);
        attr_set = 1;
    }

    k_prep<<<1, 256>>>(sigma, tmlp_W1, tmlp_b1, tmlp_W2, tmlp_b2,
                       ada1_pW, ada1_pb, ada2_pW, ada2_pb);
    k_bias_tc<<<(L*L)/128, 256>>>(pair, pairW);
    k_gemm_tc<true,false,false><<<dim3(C/128, L/128), 256, GEMM_SMEM>>>(single, single_W, single_b, nullptr, p_h, L, C, C);
    k_coord<<<L, 256>>>(x_noisy, coord_W, coord_b);

    for (int b = 0; b < NB; b++) {
        k_adaln<<<L, 256>>>(p_h, p_h1, ada1_g + b*C, ada1_b + b*C, b, 0);
        k_qkv_tc<<<dim3(C/128, L/128, 3), 256, GEMM_SMEM>>>(p_h1,
            qW + (size_t)b*C*C, kW + (size_t)b*C*C, vW + (size_t)b*C*C,
            p_q, p_k, p_v);
        k_attn_tc<<<dim3(L/128, H), 256, ATTN_SMEM>>>(b);
        k_gemm_tc<true,false,true><<<dim3(C/128, L/128), 256, GEMM_SMEM>>>(p_ao, outW + (size_t)b*C*C, outb + b*C, p_h, p_h, L, C, C);
        k_adaln<<<L, 256>>>(p_h, p_h1, ada2_g + b*C, ada2_b + b*C, b, 1);
        k_gemm_tc<true,true,false><<<dim3(4*C/128, L/128), 256, GEMM_SMEM>>>(p_h1, ffn_W1 + (size_t)b*4*C*C, ffn_b1 + b*4*C, nullptr, p_mid, L, 4*C, C);
        k_gemm_tc<true,false,true><<<dim3(C/128, L/128), 256, GEMM_SMEM>>>(p_mid, ffn_W2 + (size_t)b*4*C*C, ffn_b2 + b*C, p_h, p_h, L, C, 4*C);
    }
    k_final<<<L/8, 256>>>(x_noisy, out_W, out_b, out);
}